// round 13
// baseline (speedup 1.0000x reference)
#include <cuda_runtime.h>
#include <cuda_fp16.h>
#include <mma.h>
#include <math.h>

using namespace nvcuda;

#define BB  128
#define SS  256
#define II  512
#define HH  1024
#define OO  512
#define TT  128
#define G4H 4096
#define NSTEP (SS + TT)
#define NCTA_REC 128
#define GA 8704            // floats per packed 128x68 K-chunk tile (tf32 GEMM)
#define HA 17408           // halves per packed 128x136 K-chunk tile (fp16 GEMM)

// ---------------- static device scratch ----------------
__device__ __align__(128) float g_Ppk[(size_t)SS * 128 * 4096];   // P [s][cta][m64][col64]
__device__ __align__(128) __half g_xpk16[(size_t)256 * 4 * HA];
__device__ __align__(128) __half g_WihE16[(size_t)32 * 4 * HA];
__device__ __align__(128) __half g_Wproj16[(size_t)4 * 8 * HA];
__device__ __align__(128) __half g_Hall16[(size_t)128 * 8 * HA];  // decoder h fp16 packed
__device__ __align__(128) float g_WihDpk[(size_t)32 * 8 * GA];    // tf32 packs (Weff GEMM)
__device__ __align__(128) float g_WpTpk[(size_t)8 * 8 * GA];
__device__ __align__(128) __half g_Wt16E[(size_t)64 * 8 * 8704];  // rec W images [nt][ch][64r][136k]
__device__ __align__(128) __half g_Wt16D[(size_t)64 * 8 * 8704];
__device__ __align__(128) __half g_Wt16F[(size_t)64 * 8 * 8704];
__device__ __align__(128) __half g_hT16[2 * 2 * 8 * 128 * 72];    // [buf][mt][ch][128k][72m]
__device__ float g_benc[G4H];
__device__ float g_bdec[G4H];
__device__ float g_beff[G4H];
__device__ unsigned g_bar2[2];

// ---------------- helpers ----------------
__device__ __forceinline__ float tf32t(float x) {
    unsigned u;
    asm("cvt.rna.tf32.f32 %0, %1;" : "=r"(u) : "f"(x));
    return __uint_as_float(u);
}
__device__ __forceinline__ void mbar_init(unsigned mbar, unsigned cnt) {
    asm volatile("mbarrier.init.shared.b64 [%0], %1;" :: "r"(mbar), "r"(cnt) : "memory");
}
__device__ __forceinline__ void mbar_expect(unsigned mbar, unsigned bytes) {
    asm volatile("mbarrier.arrive.expect_tx.shared.b64 _, [%0], %1;"
                 :: "r"(mbar), "r"(bytes) : "memory");
}
__device__ __forceinline__ void mbar_wait(unsigned mbar, unsigned parity) {
    unsigned done = 0;
    while (!done) {
        asm volatile(
            "{\n\t.reg .pred p;\n\t"
            "mbarrier.try_wait.parity.acquire.cta.shared::cta.b64 p, [%1], %2, 0x989680;\n\t"
            "selp.b32 %0, 1, 0, p;\n\t}"
            : "=r"(done) : "r"(mbar), "r"(parity) : "memory");
    }
}
__device__ __forceinline__ void bulk_g2s(unsigned dst, const void* src, unsigned bytes,
                                         unsigned mbar) {
    asm volatile(
        "cp.async.bulk.shared::cluster.global.mbarrier::complete_tx::bytes [%0], [%1], %2, [%3];"
        :: "r"(dst), "l"(src), "r"(bytes), "r"(mbar) : "memory");
}

// ---------------- dual grid barrier (per-mt groups of 64 CTAs) ----------------
__device__ __forceinline__ void gridbar2(int mt, int& epoch) {
    epoch++;
    __threadfence();
    __syncthreads();
    if (threadIdx.x == 0) {
        atomicAdd(&g_bar2[mt], 1u);
        const unsigned tgt = 64u * (unsigned)epoch;
        volatile unsigned* p = &g_bar2[mt];
        while (*p < tgt) { }
    }
    __syncthreads();
}
__global__ void k_reset_bar() { g_bar2[0] = 0u; g_bar2[1] = 0u; }

// ---------------- small kernels ----------------
__global__ void k_zero(float* p, int n) {
    int i = blockIdx.x * blockDim.x + threadIdx.x;
    if (i < n) p[i] = 0.f;
}
__global__ void k_vec_add(const float* __restrict__ a, const float* __restrict__ b,
                          float* __restrict__ o, int n) {
    int i = blockIdx.x * blockDim.x + threadIdx.x;
    if (i < n) o[i] = a[i] + b[i];
}
__global__ void k_beff(const float* __restrict__ Wih, const float* __restrict__ bproj,
                       const float* __restrict__ bdec, float* __restrict__ beff) {
    int n = blockIdx.x * blockDim.x + threadIdx.x;
    if (n < G4H) {
        float s = bdec[n];
        const float* wr = Wih + (size_t)n * OO;
        #pragma unroll 8
        for (int o = 0; o < OO; o++) s += wr[o] * bproj[o];
        beff[n] = s;
    }
}
// tf32 pack: src [M][K] -> [mtile][kc64][128][68]
__global__ void k_pack(const float* __restrict__ src, float* __restrict__ dst,
                       int K, size_t total) {
    size_t i = ((size_t)blockIdx.x * 256 + threadIdx.x) * 4;
    if (i < total) {
        int r = (int)(i / (unsigned)K);
        int k = (int)(i - (size_t)r * K);
        float4 v = *(const float4*)&src[i];
        v.x = tf32t(v.x); v.y = tf32t(v.y); v.z = tf32t(v.z); v.w = tf32t(v.w);
        int nk = K >> 6;
        size_t d = ((size_t)(r >> 7) * nk + (k >> 6)) * GA + (r & 127) * 68 + (k & 63);
        *(float4*)&dst[d] = v;
    }
}
// fp16 pack: src [M][K] -> [mtile][kc128][128][136]
__global__ void k_pack16(const float* __restrict__ src, __half* __restrict__ dst,
                         int K, size_t total) {
    size_t i = ((size_t)blockIdx.x * 256 + threadIdx.x) * 4;
    if (i < total) {
        int r = (int)(i / (unsigned)K);
        int k = (int)(i - (size_t)r * K);
        float4 v = *(const float4*)&src[i];
        __half2 h0 = __floats2half2_rn(v.x, v.y);
        __half2 h1 = __floats2half2_rn(v.z, v.w);
        int nk = K >> 7;
        size_t d = ((size_t)(r >> 7) * nk + (k >> 7)) * HA + (r & 127) * 136 + (k & 127);
        *(__half2*)&dst[d]     = h0;
        *(__half2*)&dst[d + 2] = h1;
    }
}
// pack transpose of Wproj [O][H] as tf32 B operand rows n (N=1024, K=512)
__global__ void k_pack_T(const float* __restrict__ Wproj, float* __restrict__ dst) {
    int i = blockIdx.x * blockDim.x + threadIdx.x;
    if (i < HH * OO) {
        int n = i >> 9, o = i & 511;
        float v = tf32t(Wproj[(size_t)o * HH + n]);
        size_t d = ((size_t)(n >> 7) * 8 + (o >> 6)) * GA + (n & 127) * 68 + (o & 63);
        dst[d] = v;
    }
}
// W [4H][H] fp32 -> fp16 rec image [nt64][ch8][row64][136]
__global__ void k_pack_w16(const float* __restrict__ W, __half* __restrict__ dst) {
    int i = blockIdx.x * blockDim.x + threadIdx.x;
    if (i < 64 * 8 * 64 * 128) {
        int kl = i & 127, r = (i >> 7) & 63, ch = (i >> 13) & 7, nt = i >> 16;
        int gr = (r >> 4) * 1024 + nt * 16 + (r & 15);
        dst[(((size_t)nt * 8 + ch) * 64 + r) * 136 + kl] =
            __float2half(W[(size_t)gr * HH + ch * 128 + kl]);
    }
}

// ---------------- tf32 GEMM (Weff only, mode 3) ----------------
__global__ void __launch_bounds__(256) k_gemmB(
        const float* __restrict__ Apk, const float* __restrict__ Bpk,
        float* __restrict__ C, int ldc, int K,
        const float* __restrict__ bias, const float* __restrict__ addm, int mode) {
    extern __shared__ float sm[];
    unsigned sbase = (unsigned)__cvta_generic_to_shared(sm);
    unsigned barb  = sbase + 4 * GA * 4;
    const int tid = threadIdx.x;
    const int m0 = blockIdx.y * 128, n0 = blockIdx.x * 128;
    const int w = tid >> 5, wm = w >> 1, wn = w & 1;
    const int nKc = K >> 6;

    if (tid < 2) mbar_init(barb + tid * 8, 1);
    __syncthreads();

    auto issue = [&](int i) {
        if (tid == 0) {
            int st = i & 1;
            mbar_expect(barb + st * 8, 2 * GA * 4);
            bulk_g2s(sbase + (unsigned)(st * GA) * 4,
                     Apk + ((size_t)blockIdx.y * nKc + i) * GA, GA * 4, barb + st * 8);
            bulk_g2s(sbase + (unsigned)((2 + st) * GA) * 4,
                     Bpk + ((size_t)blockIdx.x * nKc + i) * GA, GA * 4, barb + st * 8);
        }
    };

    wmma::fragment<wmma::accumulator, 16, 16, 8, float> acc[2][4];
    #pragma unroll
    for (int i = 0; i < 2; i++)
        #pragma unroll
        for (int j = 0; j < 4; j++) wmma::fill_fragment(acc[i][j], 0.f);

    issue(0);
    if (nKc > 1) issue(1);

    for (int it = 0; it < nKc; it++) {
        int st = it & 1;
        mbar_wait(barb + st * 8, (it >> 1) & 1);
        const float* a = sm + st * GA;
        const float* b = sm + (2 + st) * GA;
        #pragma unroll
        for (int kk = 0; kk < 8; kk++) {
            wmma::fragment<wmma::matrix_a, 16, 16, 8, wmma::precision::tf32, wmma::row_major> a0, a1;
            wmma::fragment<wmma::matrix_b, 16, 16, 8, wmma::precision::tf32, wmma::col_major> bf[4];
            wmma::load_matrix_sync(a0, &a[(wm * 32) * 68 + kk * 8], 68);
            wmma::load_matrix_sync(a1, &a[(wm * 32 + 16) * 68 + kk * 8], 68);
            #pragma unroll
            for (int t = 0; t < 4; t++)
                wmma::load_matrix_sync(bf[t], &b[(wn * 64 + t * 16) * 68 + kk * 8], 68);
            #pragma unroll
            for (int t = 0; t < 4; t++) {
                wmma::mma_sync(acc[0][t], a0, bf[t], acc[0][t]);
                wmma::mma_sync(acc[1][t], a1, bf[t], acc[1][t]);
            }
        }
        __syncthreads();
        if (it + 2 < nKc) issue(it + 2);
    }

    float* sC = sm;
    #pragma unroll
    for (int i = 0; i < 2; i++)
        #pragma unroll
        for (int t = 0; t < 4; t++)
            wmma::store_matrix_sync(&sC[(wm * 32 + i * 16) * 132 + wn * 64 + t * 16],
                                    acc[i][t], 132, wmma::mem_row_major);
    __syncthreads();

    for (int idx = tid; idx < 128 * 128; idx += 256) {
        int m = idx >> 7, n = idx & 127;
        float v = sC[m * 132 + n];
        if (bias) v += bias[n0 + n];
        {   // mode 3: Weff -> fp16 rec image (+Whh_d)
            int gr = m0 + m, k = n0 + n;
            v += addm[(size_t)gr * ldc + k];
            int g = gr >> 10, cc = gr & 1023, nt2 = cc >> 4, r = g * 16 + (cc & 15);
            ((__half*)C)[(((size_t)nt2 * 8 + (k >> 7)) * 64 + r) * 136 + (k & 127)] =
                __float2half(v);
        }
    }
}

// ---------------- fp16 GEMM on packed operands ----------------
// C = A * B^T. mode 1: P store (+bias), coalesced [s][cta][m][col]. mode 2: final out remap (+bias).
__global__ void __launch_bounds__(256) k_gemmH(
        const __half* __restrict__ Apk, const __half* __restrict__ Bpk,
        float* __restrict__ C, int K,
        const float* __restrict__ bias, int mode) {
    extern __shared__ char smh[];
    __half* sm = (__half*)smh;
    unsigned sbase = (unsigned)__cvta_generic_to_shared(smh);
    unsigned barb  = sbase + 4 * HA * 2;
    const int tid = threadIdx.x;
    const int m0 = blockIdx.y * 128, n0 = blockIdx.x * 128;
    const int w = tid >> 5, wm = w >> 1, wn = w & 1;
    const int nKc = K >> 7;

    if (tid < 2) mbar_init(barb + tid * 8, 1);
    __syncthreads();

    auto issue = [&](int i) {
        if (tid == 0) {
            int st = i & 1;
            mbar_expect(barb + st * 8, 2 * HA * 2);
            bulk_g2s(sbase + (unsigned)(st * HA) * 2,
                     Apk + ((size_t)blockIdx.y * nKc + i) * HA, HA * 2, barb + st * 8);
            bulk_g2s(sbase + (unsigned)((2 + st) * HA) * 2,
                     Bpk + ((size_t)blockIdx.x * nKc + i) * HA, HA * 2, barb + st * 8);
        }
    };

    wmma::fragment<wmma::accumulator, 16, 16, 16, float> acc[2][4];
    #pragma unroll
    for (int i = 0; i < 2; i++)
        #pragma unroll
        for (int j = 0; j < 4; j++) wmma::fill_fragment(acc[i][j], 0.f);

    issue(0);
    if (nKc > 1) issue(1);

    for (int it = 0; it < nKc; it++) {
        int st = it & 1;
        mbar_wait(barb + st * 8, (it >> 1) & 1);
        const __half* a = sm + st * HA;
        const __half* b = sm + (2 + st) * HA;
        #pragma unroll
        for (int kk = 0; kk < 8; kk++) {
            wmma::fragment<wmma::matrix_a, 16, 16, 16, __half, wmma::row_major> a0, a1;
            wmma::fragment<wmma::matrix_b, 16, 16, 16, __half, wmma::col_major> bf[4];
            wmma::load_matrix_sync(a0, &a[(size_t)(wm * 32) * 136 + kk * 16], 136);
            wmma::load_matrix_sync(a1, &a[(size_t)(wm * 32 + 16) * 136 + kk * 16], 136);
            #pragma unroll
            for (int t = 0; t < 4; t++)
                wmma::load_matrix_sync(bf[t], &b[(size_t)(wn * 64 + t * 16) * 136 + kk * 16], 136);
            #pragma unroll
            for (int t = 0; t < 4; t++) {
                wmma::mma_sync(acc[0][t], a0, bf[t], acc[0][t]);
                wmma::mma_sync(acc[1][t], a1, bf[t], acc[1][t]);
            }
        }
        __syncthreads();
        if (it + 2 < nKc) issue(it + 2);
    }

    float* sC = (float*)smh;
    #pragma unroll
    for (int i = 0; i < 2; i++)
        #pragma unroll
        for (int t = 0; t < 4; t++)
            wmma::store_matrix_sync(&sC[(wm * 32 + i * 16) * 132 + wn * 64 + t * 16],
                                    acc[i][t], 132, wmma::mem_row_major);
    __syncthreads();

    for (int idx = tid; idx < 128 * 128; idx += 256) {
        int n = idx & 127, m = idx >> 7;          // n-minor: coalesced stores
        float v = sC[m * 132 + n];
        if (bias) v += bias[n0 + n];
        if (mode == 1) {            // P: GEMM row r = b*256+s -> Ppk[s][cta][m][col]
            int r = m0 + m, ng = n0 + n;
            int bb = r >> 8, s = r & 255;
            int g = ng >> 10, cc = ng & 1023, nt2 = cc >> 4, j = cc & 15;
            int cta = 2 * nt2 + (bb >> 6);
            C[(((size_t)s * 128 + cta) * 64 + (bb & 63)) * 64 + g * 16 + j] = v;
        } else {                    // final: r = t*128+b -> out[b][t][n]
            int r = m0 + m; int b = r & 127, t = r >> 7;
            C[((size_t)b * TT + t) * OO + n0 + n] = v;
        }
    }
}

// ---------------- persistent fp16 recurrence (2m x 4n warps, prefetch-over-barrier) --
// smem bytes: A 2x18432 @0 | Wres 8x17408 @36864 | sC @176128 | bars @193536
#define RS_W    36864u
#define RS_C    176128u
#define RS_BAR  193536u
#define RS_SMEM 193600

__global__ void __launch_bounds__(256, 1) k_rec16(
        const float* __restrict__ Ppk,
        const __half* __restrict__ WtE,
        const __half* __restrict__ WtD,
        const __half* __restrict__ WtF,
        const float* __restrict__ bdec,
        const float* __restrict__ beff,
        __half* __restrict__ hT16,
        __half* __restrict__ Hall16) {
    extern __shared__ __align__(128) char smc[];
    __half* sA = (__half*)smc;
    __half* sW = (__half*)(smc + RS_W);
    float* sC = (float*)(smc + RS_C);
    unsigned sb   = (unsigned)__cvta_generic_to_shared(smc);
    unsigned barb = sb + RS_BAR;

    const int tid = threadIdx.x, cta = blockIdx.x;
    const int mt = cta & 1, nt = cta >> 1, nb = nt * 16;
    const int w = tid >> 5;
    const int wm = w & 1, wn2 = w >> 1;         // 2m x 4n warp tiling
    const int mloc = tid & 63, j0 = tid >> 6;

    if (tid < 2) mbar_init(barb + tid * 8, 1);
    __syncthreads();

    float cst[4];
    #pragma unroll
    for (int jj = 0; jj < 4; jj++) cst[jj] = 0.f;

    int epoch = 0;

    // register prefetch of P / bias for step ss (4x float4 per thread)
    float pv[16];
    auto pfetch = [&](int ss) {
        if (ss < SS) {
            const float* Ps = Ppk + ((size_t)ss * 128 + cta) * 4096 + mloc * 64 + 4 * j0;
            #pragma unroll
            for (int g = 0; g < 4; g++) {
                float4 t4 = *(const float4*)&Ps[g * 16];
                pv[g * 4 + 0] = t4.x; pv[g * 4 + 1] = t4.y;
                pv[g * 4 + 2] = t4.z; pv[g * 4 + 3] = t4.w;
            }
        } else {
            const float* gb = (ss == SS) ? bdec : beff;
            #pragma unroll
            for (int g = 0; g < 4; g++) {
                float4 t4 = *(const float4*)&gb[g * 1024 + nb + 4 * j0];
                pv[g * 4 + 0] = t4.x; pv[g * 4 + 1] = t4.y;
                pv[g * 4 + 2] = t4.z; pv[g * 4 + 3] = t4.w;
            }
        }
    };
    pfetch(0);

    for (int s = 0; s < NSTEP; s++) {
        const bool wload = (s == 0) || (s == SS) || (s == SS + 1);
        const __half* Wsrc = ((s < SS) ? WtE : ((s == SS) ? WtD : WtF))
                             + (size_t)nt * 69632;
        const __half* Asrc = hT16 + (size_t)((s & 1) * 2 + mt) * 73728;
        __half* Adst = hT16 + (size_t)(((s + 1) & 1) * 2 + mt) * 73728;

        auto issue = [&](int c) {
            int st = c & 1;
            unsigned tx = 18432u + (wload ? 17408u : 0u);
            mbar_expect(barb + st * 8, tx);
            bulk_g2s(sb + (unsigned)(st * 18432), Asrc + (size_t)c * 9216,
                     18432, barb + st * 8);
            if (wload)
                bulk_g2s(sb + RS_W + (unsigned)c * 17408, Wsrc + (size_t)c * 8704,
                         17408, barb + st * 8);
        };

        if (tid == 0) { issue(0); issue(1); }

        wmma::fragment<wmma::accumulator, 16, 16, 16, float> acc[2];
        wmma::fill_fragment(acc[0], 0.f);
        wmma::fill_fragment(acc[1], 0.f);

        for (int c = 0; c < 8; c++) {
            int st = c & 1;
            mbar_wait(barb + st * 8, (c >> 1) & 1);
            const __half* A = sA + st * 9216;           // [k128][72m]
            const __half* Wc = sW + (size_t)c * 8704;   // [64r][136k]
            #pragma unroll
            for (int kk = 0; kk < 8; kk++) {
                int k0 = kk * 16;
                wmma::fragment<wmma::matrix_a, 16, 16, 16, __half, wmma::col_major> a0, a1;
                wmma::fragment<wmma::matrix_b, 16, 16, 16, __half, wmma::col_major> b0;
                wmma::load_matrix_sync(a0, &A[(size_t)k0 * 72 + wm * 32], 72);
                wmma::load_matrix_sync(a1, &A[(size_t)k0 * 72 + wm * 32 + 16], 72);
                wmma::load_matrix_sync(b0, &Wc[(size_t)(wn2 * 16) * 136 + k0], 136);
                wmma::mma_sync(acc[0], a0, b0, acc[0]);
                wmma::mma_sync(acc[1], a1, b0, acc[1]);
            }
            __syncthreads();
            if (tid == 0 && c + 2 < 8) issue(c + 2);
        }

        #pragma unroll
        for (int i = 0; i < 2; i++)
            wmma::store_matrix_sync(&sC[(wm * 32 + i * 16) * 68 + wn2 * 16],
                                    acc[i], 68, wmma::mem_row_major);
        __syncthreads();

        // pointwise: thread (mloc, j0) owns j = 4*j0 + jj (matches float4 P layout)
        #pragma unroll
        for (int jj = 0; jj < 4; jj++) {
            int j = 4 * j0 + jj;
            int n = nb + j;
            float Gi = sC[mloc * 68 + j]      + pv[jj];
            float Gf = sC[mloc * 68 + 16 + j] + pv[4 + jj];
            float Gg = sC[mloc * 68 + 32 + j] + pv[8 + jj];
            float Go = sC[mloc * 68 + 48 + j] + pv[12 + jj];
            float si = 1.f / (1.f + __expf(-Gi));
            float sf = 1.f / (1.f + __expf(-Gf));
            float so = 1.f / (1.f + __expf(-Go));
            float tg = __fdividef(2.f, 1.f + __expf(-2.f * Gg)) - 1.f;
            float cn = sf * cst[jj] + si * tg;
            cst[jj] = cn;
            float tc = __fdividef(2.f, 1.f + __expf(-2.f * cn)) - 1.f;
            float hn = so * tc;
            Adst[((size_t)(n >> 7) * 128 + (n & 127)) * 72 + mloc] = __float2half(hn);
            if (s >= SS) {
                int t = s - SS;
                Hall16[(((size_t)t * 8 + (n >> 7)) * 128 + mt * 64 + mloc) * 136 + (n & 127)]
                    = __float2half(hn);
            }
        }

        // prefetch next step's P/bias NOW — latency hides behind the barrier + MMAs
        if (s + 1 < NSTEP) pfetch(s + 1);

        if (s < NSTEP - 1) gridbar2(mt, epoch);
    }
}

// ---------------- host launch ----------------
extern "C" void kernel_launch(void* const* d_in, const int* in_sizes, int n_in,
                              void* d_out, int out_size) {
    int wbase = (n_in >= 12 && in_sizes[1] == 1) ? 2 : 1;

    const float* x     = (const float*)d_in[0];
    const float* Wih_e = (const float*)d_in[wbase + 0];
    const float* Whh_e = (const float*)d_in[wbase + 1];
    const float* bih_e = (const float*)d_in[wbase + 2];
    const float* bhh_e = (const float*)d_in[wbase + 3];
    const float* Wih_d = (const float*)d_in[wbase + 4];
    const float* Whh_d = (const float*)d_in[wbase + 5];
    const float* bih_d = (const float*)d_in[wbase + 6];
    const float* bhh_d = (const float*)d_in[wbase + 7];
    const float* Wproj = (const float*)d_in[wbase + 8];
    const float* bproj = (const float*)d_in[wbase + 9];
    float* out = (float*)d_out;

    float *Ppk, *WihDpk, *WpTpk, *benc, *bdec, *beff;
    __half *xpk16, *WihE16, *Wproj16, *Hall16, *WtE, *WtD, *WtF, *hT16;
    cudaGetSymbolAddress((void**)&Ppk,     g_Ppk);
    cudaGetSymbolAddress((void**)&xpk16,   g_xpk16);
    cudaGetSymbolAddress((void**)&WihE16,  g_WihE16);
    cudaGetSymbolAddress((void**)&Wproj16, g_Wproj16);
    cudaGetSymbolAddress((void**)&Hall16,  g_Hall16);
    cudaGetSymbolAddress((void**)&WihDpk,  g_WihDpk);
    cudaGetSymbolAddress((void**)&WpTpk,   g_WpTpk);
    cudaGetSymbolAddress((void**)&WtE,     g_Wt16E);
    cudaGetSymbolAddress((void**)&WtD,     g_Wt16D);
    cudaGetSymbolAddress((void**)&WtF,     g_Wt16F);
    cudaGetSymbolAddress((void**)&hT16,    g_hT16);
    cudaGetSymbolAddress((void**)&benc,    g_benc);
    cudaGetSymbolAddress((void**)&bdec,    g_bdec);
    cudaGetSymbolAddress((void**)&beff,    g_beff);

    const int gemmSmemB = 4 * GA * 4 + 64;
    const int gemmSmemH = 4 * HA * 2 + 64;
    cudaFuncSetAttribute(k_gemmB, cudaFuncAttributeMaxDynamicSharedMemorySize, gemmSmemB);
    cudaFuncSetAttribute(k_gemmH, cudaFuncAttributeMaxDynamicSharedMemorySize, gemmSmemH);
    cudaFuncSetAttribute(k_rec16, cudaFuncAttributeMaxDynamicSharedMemorySize, RS_SMEM);

    // biases
    k_vec_add<<<16, 256>>>(bih_e, bhh_e, benc, G4H);
    k_vec_add<<<16, 256>>>(bih_d, bhh_d, bdec, G4H);
    k_beff<<<16, 256>>>(Wih_d, bproj, bdec, beff);

    // fp16 packs (P + final GEMM operands)
    k_pack16<<<(int)(((size_t)BB * SS * II / 4 + 255) / 256), 256>>>(
        x, xpk16, II, (size_t)BB * SS * II);
    k_pack16<<<(int)(((size_t)G4H * II / 4 + 255) / 256), 256>>>(
        Wih_e, WihE16, II, (size_t)G4H * II);
    k_pack16<<<(int)(((size_t)OO * HH / 4 + 255) / 256), 256>>>(
        Wproj, Wproj16, HH, (size_t)OO * HH);
    // tf32 packs (Weff GEMM operands)
    k_pack<<<(int)(((size_t)G4H * OO / 4 + 255) / 256), 256>>>(
        Wih_d, WihDpk, OO, (size_t)G4H * OO);
    k_pack_T<<<(HH * OO + 255) / 256, 256>>>(Wproj, WpTpk);
    // rec weight images
    k_pack_w16<<<(64 * 8 * 64 * 128) / 256, 256>>>(Whh_e, WtE);
    k_pack_w16<<<(64 * 8 * 64 * 128) / 256, 256>>>(Whh_d, WtD);

    // W_eff = W_ih_dec @ W_proj + W_hh_dec -> fp16 rec image (tf32 GEMM, mode 3)
    k_gemmB<<<dim3(HH / 128, G4H / 128), 256, gemmSmemB>>>(
        WihDpk, WpTpk, (float*)WtF, HH, OO, nullptr, Whh_d, 3);

    // P = X @ W_ih_enc^T + b_enc -> Ppk (fp16 GEMM, mode 1, coalesced store)
    k_gemmH<<<dim3(G4H / 128, (BB * SS) / 128), 256, gemmSmemH>>>(
        xpk16, WihE16, Ppk, II, benc, 1);

    // zero h images, reset barriers, run the 384-step recurrence
    k_zero<<<(2 * 2 * 8 * 128 * 72 / 2 + 255) / 256, 256>>>((float*)hT16,
                                                            2 * 2 * 8 * 128 * 72 / 2);
    k_reset_bar<<<1, 1>>>();
    k_rec16<<<NCTA_REC, 256, RS_SMEM>>>(Ppk, WtE, WtD, WtF, bdec, beff, hT16, Hall16);

    // Y = Hall @ W_proj^T + b_proj -> out[b][t][o] (fp16 GEMM, mode 2)
    k_gemmH<<<dim3(OO / 128, (BB * TT) / 128), 256, gemmSmemH>>>(
        Hall16, Wproj16, out, HH, bproj, 2);
}

// round 14
// speedup vs baseline: 1.0553x; 1.0553x over previous
#include <cuda_runtime.h>
#include <cuda_fp16.h>
#include <mma.h>
#include <math.h>

using namespace nvcuda;

#define BB  128
#define SS  256
#define II  512
#define HH  1024
#define OO  512
#define TT  128
#define G4H 4096
#define NSTEP (SS + TT)
#define NCTA_REC 128
#define GA 8704            // floats per packed 128x68 K-chunk tile (tf32 GEMM)
#define HA 17408           // halves per packed 128x136 K-chunk tile (fp16 GEMM)

// ---------------- static device scratch ----------------
__device__ __align__(128) float g_Ppk[(size_t)SS * 128 * 4096];   // P [s][cta][m64][col64]
__device__ __align__(128) __half g_xpk16[(size_t)256 * 4 * HA];
__device__ __align__(128) __half g_WihE16[(size_t)32 * 4 * HA];
__device__ __align__(128) __half g_Wproj16[(size_t)4 * 8 * HA];
__device__ __align__(128) __half g_Hall16[(size_t)128 * 8 * HA];  // decoder h fp16 packed
__device__ __align__(128) float g_WihDpk[(size_t)32 * 8 * GA];    // tf32 packs (Weff GEMM)
__device__ __align__(128) float g_WpTpk[(size_t)8 * 8 * GA];
__device__ __align__(128) __half g_Wt16E[(size_t)64 * 8 * 8704];  // rec W images [nt][ch][64r][136k]
__device__ __align__(128) __half g_Wt16D[(size_t)64 * 8 * 8704];
__device__ __align__(128) __half g_Wt16F[(size_t)64 * 8 * 8704];
__device__ __align__(128) __half g_hT16[2 * 2 * 8 * 128 * 72];    // [buf][mt][ch][128k][72m]
__device__ float g_benc[G4H];
__device__ float g_bdec[G4H];
__device__ float g_beff[G4H];
__device__ unsigned g_bar2[2];

// ---------------- helpers ----------------
__device__ __forceinline__ float tf32t(float x) {
    unsigned u;
    asm("cvt.rna.tf32.f32 %0, %1;" : "=r"(u) : "f"(x));
    return __uint_as_float(u);
}
__device__ __forceinline__ void mbar_init(unsigned mbar, unsigned cnt) {
    asm volatile("mbarrier.init.shared.b64 [%0], %1;" :: "r"(mbar), "r"(cnt) : "memory");
}
__device__ __forceinline__ void mbar_expect(unsigned mbar, unsigned bytes) {
    asm volatile("mbarrier.arrive.expect_tx.shared.b64 _, [%0], %1;"
                 :: "r"(mbar), "r"(bytes) : "memory");
}
__device__ __forceinline__ void mbar_wait(unsigned mbar, unsigned parity) {
    unsigned done = 0;
    while (!done) {
        asm volatile(
            "{\n\t.reg .pred p;\n\t"
            "mbarrier.try_wait.parity.acquire.cta.shared::cta.b64 p, [%1], %2, 0x989680;\n\t"
            "selp.b32 %0, 1, 0, p;\n\t}"
            : "=r"(done) : "r"(mbar), "r"(parity) : "memory");
    }
}
__device__ __forceinline__ void bulk_g2s(unsigned dst, const void* src, unsigned bytes,
                                         unsigned mbar) {
    asm volatile(
        "cp.async.bulk.shared::cluster.global.mbarrier::complete_tx::bytes [%0], [%1], %2, [%3];"
        :: "r"(dst), "l"(src), "r"(bytes), "r"(mbar) : "memory");
}

// ---------------- dual grid barrier (per-mt groups of 64 CTAs) ----------------
__device__ __forceinline__ void gridbar2(int mt, int& epoch) {
    epoch++;
    __threadfence();
    __syncthreads();
    if (threadIdx.x == 0) {
        atomicAdd(&g_bar2[mt], 1u);
        const unsigned tgt = 64u * (unsigned)epoch;
        volatile unsigned* p = &g_bar2[mt];
        while (*p < tgt) { }
    }
    __syncthreads();
}
__global__ void k_reset_bar() { g_bar2[0] = 0u; g_bar2[1] = 0u; }

// ---------------- small kernels ----------------
__global__ void k_zero(float* p, int n) {
    int i = blockIdx.x * blockDim.x + threadIdx.x;
    if (i < n) p[i] = 0.f;
}
__global__ void k_vec_add(const float* __restrict__ a, const float* __restrict__ b,
                          float* __restrict__ o, int n) {
    int i = blockIdx.x * blockDim.x + threadIdx.x;
    if (i < n) o[i] = a[i] + b[i];
}
__global__ void k_beff(const float* __restrict__ Wih, const float* __restrict__ bproj,
                       const float* __restrict__ bdec, float* __restrict__ beff) {
    int n = blockIdx.x * blockDim.x + threadIdx.x;
    if (n < G4H) {
        float s = bdec[n];
        const float* wr = Wih + (size_t)n * OO;
        #pragma unroll 8
        for (int o = 0; o < OO; o++) s += wr[o] * bproj[o];
        beff[n] = s;
    }
}
// tf32 pack: src [M][K] -> [mtile][kc64][128][68]
__global__ void k_pack(const float* __restrict__ src, float* __restrict__ dst,
                       int K, size_t total) {
    size_t i = ((size_t)blockIdx.x * 256 + threadIdx.x) * 4;
    if (i < total) {
        int r = (int)(i / (unsigned)K);
        int k = (int)(i - (size_t)r * K);
        float4 v = *(const float4*)&src[i];
        v.x = tf32t(v.x); v.y = tf32t(v.y); v.z = tf32t(v.z); v.w = tf32t(v.w);
        int nk = K >> 6;
        size_t d = ((size_t)(r >> 7) * nk + (k >> 6)) * GA + (r & 127) * 68 + (k & 63);
        *(float4*)&dst[d] = v;
    }
}
// fp16 pack: src [M][K] -> [mtile][kc128][128][136]
__global__ void k_pack16(const float* __restrict__ src, __half* __restrict__ dst,
                         int K, size_t total) {
    size_t i = ((size_t)blockIdx.x * 256 + threadIdx.x) * 4;
    if (i < total) {
        int r = (int)(i / (unsigned)K);
        int k = (int)(i - (size_t)r * K);
        float4 v = *(const float4*)&src[i];
        __half2 h0 = __floats2half2_rn(v.x, v.y);
        __half2 h1 = __floats2half2_rn(v.z, v.w);
        int nk = K >> 7;
        size_t d = ((size_t)(r >> 7) * nk + (k >> 7)) * HA + (r & 127) * 136 + (k & 127);
        *(__half2*)&dst[d]     = h0;
        *(__half2*)&dst[d + 2] = h1;
    }
}
// pack transpose of Wproj [O][H] as tf32 B operand rows n (N=1024, K=512)
__global__ void k_pack_T(const float* __restrict__ Wproj, float* __restrict__ dst) {
    int i = blockIdx.x * blockDim.x + threadIdx.x;
    if (i < HH * OO) {
        int n = i >> 9, o = i & 511;
        float v = tf32t(Wproj[(size_t)o * HH + n]);
        size_t d = ((size_t)(n >> 7) * 8 + (o >> 6)) * GA + (n & 127) * 68 + (o & 63);
        dst[d] = v;
    }
}
// W [4H][H] fp32 -> fp16 rec image [nt64][ch8][row64][136]
__global__ void k_pack_w16(const float* __restrict__ W, __half* __restrict__ dst) {
    int i = blockIdx.x * blockDim.x + threadIdx.x;
    if (i < 64 * 8 * 64 * 128) {
        int kl = i & 127, r = (i >> 7) & 63, ch = (i >> 13) & 7, nt = i >> 16;
        int gr = (r >> 4) * 1024 + nt * 16 + (r & 15);
        dst[(((size_t)nt * 8 + ch) * 64 + r) * 136 + kl] =
            __float2half(W[(size_t)gr * HH + ch * 128 + kl]);
    }
}

// ---------------- tf32 GEMM (Weff only, mode 3) ----------------
__global__ void __launch_bounds__(256) k_gemmB(
        const float* __restrict__ Apk, const float* __restrict__ Bpk,
        float* __restrict__ C, int ldc, int K,
        const float* __restrict__ bias, const float* __restrict__ addm, int mode) {
    extern __shared__ float sm[];
    unsigned sbase = (unsigned)__cvta_generic_to_shared(sm);
    unsigned barb  = sbase + 4 * GA * 4;
    const int tid = threadIdx.x;
    const int m0 = blockIdx.y * 128, n0 = blockIdx.x * 128;
    const int w = tid >> 5, wm = w >> 1, wn = w & 1;
    const int nKc = K >> 6;

    if (tid < 2) mbar_init(barb + tid * 8, 1);
    __syncthreads();

    auto issue = [&](int i) {
        if (tid == 0) {
            int st = i & 1;
            mbar_expect(barb + st * 8, 2 * GA * 4);
            bulk_g2s(sbase + (unsigned)(st * GA) * 4,
                     Apk + ((size_t)blockIdx.y * nKc + i) * GA, GA * 4, barb + st * 8);
            bulk_g2s(sbase + (unsigned)((2 + st) * GA) * 4,
                     Bpk + ((size_t)blockIdx.x * nKc + i) * GA, GA * 4, barb + st * 8);
        }
    };

    wmma::fragment<wmma::accumulator, 16, 16, 8, float> acc[2][4];
    #pragma unroll
    for (int i = 0; i < 2; i++)
        #pragma unroll
        for (int j = 0; j < 4; j++) wmma::fill_fragment(acc[i][j], 0.f);

    issue(0);
    if (nKc > 1) issue(1);

    for (int it = 0; it < nKc; it++) {
        int st = it & 1;
        mbar_wait(barb + st * 8, (it >> 1) & 1);
        const float* a = sm + st * GA;
        const float* b = sm + (2 + st) * GA;
        #pragma unroll
        for (int kk = 0; kk < 8; kk++) {
            wmma::fragment<wmma::matrix_a, 16, 16, 8, wmma::precision::tf32, wmma::row_major> a0, a1;
            wmma::fragment<wmma::matrix_b, 16, 16, 8, wmma::precision::tf32, wmma::col_major> bf[4];
            wmma::load_matrix_sync(a0, &a[(wm * 32) * 68 + kk * 8], 68);
            wmma::load_matrix_sync(a1, &a[(wm * 32 + 16) * 68 + kk * 8], 68);
            #pragma unroll
            for (int t = 0; t < 4; t++)
                wmma::load_matrix_sync(bf[t], &b[(wn * 64 + t * 16) * 68 + kk * 8], 68);
            #pragma unroll
            for (int t = 0; t < 4; t++) {
                wmma::mma_sync(acc[0][t], a0, bf[t], acc[0][t]);
                wmma::mma_sync(acc[1][t], a1, bf[t], acc[1][t]);
            }
        }
        __syncthreads();
        if (it + 2 < nKc) issue(it + 2);
    }

    float* sC = sm;
    #pragma unroll
    for (int i = 0; i < 2; i++)
        #pragma unroll
        for (int t = 0; t < 4; t++)
            wmma::store_matrix_sync(&sC[(wm * 32 + i * 16) * 132 + wn * 64 + t * 16],
                                    acc[i][t], 132, wmma::mem_row_major);
    __syncthreads();

    for (int idx = tid; idx < 128 * 128; idx += 256) {
        int m = idx >> 7, n = idx & 127;
        float v = sC[m * 132 + n];
        if (bias) v += bias[n0 + n];
        {   // mode 3: Weff -> fp16 rec image (+Whh_d)
            int gr = m0 + m, k = n0 + n;
            v += addm[(size_t)gr * ldc + k];
            int g = gr >> 10, cc = gr & 1023, nt2 = cc >> 4, r = g * 16 + (cc & 15);
            ((__half*)C)[(((size_t)nt2 * 8 + (k >> 7)) * 64 + r) * 136 + (k & 127)] =
                __float2half(v);
        }
    }
}

// ---------------- fp16 GEMM on packed operands ----------------
// C = A * B^T. mode 1: P store (+bias), coalesced [s][cta][m][col]. mode 2: final out remap (+bias).
__global__ void __launch_bounds__(256) k_gemmH(
        const __half* __restrict__ Apk, const __half* __restrict__ Bpk,
        float* __restrict__ C, int K,
        const float* __restrict__ bias, int mode) {
    extern __shared__ char smh[];
    __half* sm = (__half*)smh;
    unsigned sbase = (unsigned)__cvta_generic_to_shared(smh);
    unsigned barb  = sbase + 4 * HA * 2;
    const int tid = threadIdx.x;
    const int m0 = blockIdx.y * 128, n0 = blockIdx.x * 128;
    const int w = tid >> 5, wm = w >> 1, wn = w & 1;
    const int nKc = K >> 7;

    if (tid < 2) mbar_init(barb + tid * 8, 1);
    __syncthreads();

    auto issue = [&](int i) {
        if (tid == 0) {
            int st = i & 1;
            mbar_expect(barb + st * 8, 2 * HA * 2);
            bulk_g2s(sbase + (unsigned)(st * HA) * 2,
                     Apk + ((size_t)blockIdx.y * nKc + i) * HA, HA * 2, barb + st * 8);
            bulk_g2s(sbase + (unsigned)((2 + st) * HA) * 2,
                     Bpk + ((size_t)blockIdx.x * nKc + i) * HA, HA * 2, barb + st * 8);
        }
    };

    wmma::fragment<wmma::accumulator, 16, 16, 16, float> acc[2][4];
    #pragma unroll
    for (int i = 0; i < 2; i++)
        #pragma unroll
        for (int j = 0; j < 4; j++) wmma::fill_fragment(acc[i][j], 0.f);

    issue(0);
    if (nKc > 1) issue(1);

    for (int it = 0; it < nKc; it++) {
        int st = it & 1;
        mbar_wait(barb + st * 8, (it >> 1) & 1);
        const __half* a = sm + st * HA;
        const __half* b = sm + (2 + st) * HA;
        #pragma unroll
        for (int kk = 0; kk < 8; kk++) {
            wmma::fragment<wmma::matrix_a, 16, 16, 16, __half, wmma::row_major> a0, a1;
            wmma::fragment<wmma::matrix_b, 16, 16, 16, __half, wmma::col_major> bf[4];
            wmma::load_matrix_sync(a0, &a[(size_t)(wm * 32) * 136 + kk * 16], 136);
            wmma::load_matrix_sync(a1, &a[(size_t)(wm * 32 + 16) * 136 + kk * 16], 136);
            #pragma unroll
            for (int t = 0; t < 4; t++)
                wmma::load_matrix_sync(bf[t], &b[(size_t)(wn * 64 + t * 16) * 136 + kk * 16], 136);
            #pragma unroll
            for (int t = 0; t < 4; t++) {
                wmma::mma_sync(acc[0][t], a0, bf[t], acc[0][t]);
                wmma::mma_sync(acc[1][t], a1, bf[t], acc[1][t]);
            }
        }
        __syncthreads();
        if (it + 2 < nKc) issue(it + 2);
    }

    float* sC = (float*)smh;
    #pragma unroll
    for (int i = 0; i < 2; i++)
        #pragma unroll
        for (int t = 0; t < 4; t++)
            wmma::store_matrix_sync(&sC[(wm * 32 + i * 16) * 132 + wn * 64 + t * 16],
                                    acc[i][t], 132, wmma::mem_row_major);
    __syncthreads();

    for (int idx = tid; idx < 128 * 128; idx += 256) {
        int n = idx & 127, m = idx >> 7;          // n-minor: coalesced stores
        float v = sC[m * 132 + n];
        if (bias) v += bias[n0 + n];
        if (mode == 1) {            // P: GEMM row r = b*256+s -> Ppk[s][cta][m][col]
            int r = m0 + m, ng = n0 + n;
            int bb = r >> 8, s = r & 255;
            int g = ng >> 10, cc = ng & 1023, nt2 = cc >> 4, j = cc & 15;
            int cta = 2 * nt2 + (bb >> 6);
            C[(((size_t)s * 128 + cta) * 64 + (bb & 63)) * 64 + g * 16 + j] = v;
        } else {                    // final: r = t*128+b -> out[b][t][n]
            int r = m0 + m; int b = r & 127, t = r >> 7;
            C[((size_t)b * TT + t) * OO + n0 + n] = v;
        }
    }
}

// ---------------- persistent fp16 recurrence (2-stage, k-split, prefetch-over-barrier)
// smem bytes: A 2x18432 @0 | Wres 8x17408 @36864 | sC0 @176128 | sC1 @193536 | bars @210944
#define RS_W    36864u
#define RS_C0   176128u
#define RS_C1   193536u
#define RS_BAR  210944u
#define RS_SMEM 210960

__global__ void __launch_bounds__(256, 1) k_rec16(
        const float* __restrict__ Ppk,
        const __half* __restrict__ WtE,
        const __half* __restrict__ WtD,
        const __half* __restrict__ WtF,
        const float* __restrict__ bdec,
        const float* __restrict__ beff,
        __half* __restrict__ hT16,
        __half* __restrict__ Hall16) {
    extern __shared__ __align__(128) char smc[];
    __half* sA = (__half*)smc;
    __half* sW = (__half*)(smc + RS_W);
    float* sC0 = (float*)(smc + RS_C0);
    float* sC1 = (float*)(smc + RS_C1);
    unsigned sb   = (unsigned)__cvta_generic_to_shared(smc);
    unsigned barb = sb + RS_BAR;

    const int tid = threadIdx.x, cta = blockIdx.x;
    const int mt = cta & 1, nt = cta >> 1, nb = nt * 16;
    const int w = tid >> 5;
    const int wm = w & 1, wn = (w >> 1) & 1, wk = w >> 2;
    const int mloc = tid & 63, j0 = tid >> 6;

    if (tid < 2) mbar_init(barb + tid * 8, 1);
    __syncthreads();

    float cst[4];
    #pragma unroll
    for (int jj = 0; jj < 4; jj++) cst[jj] = 0.f;

    int epoch = 0;

    // register prefetch of P / bias for step ss (4x float4 per thread)
    float pv[16];
    auto pfetch = [&](int ss) {
        if (ss < SS) {
            const float* Ps = Ppk + ((size_t)ss * 128 + cta) * 4096 + mloc * 64 + 4 * j0;
            #pragma unroll
            for (int g = 0; g < 4; g++) {
                float4 t4 = *(const float4*)&Ps[g * 16];
                pv[g * 4 + 0] = t4.x; pv[g * 4 + 1] = t4.y;
                pv[g * 4 + 2] = t4.z; pv[g * 4 + 3] = t4.w;
            }
        } else {
            const float* gb = (ss == SS) ? bdec : beff;
            #pragma unroll
            for (int g = 0; g < 4; g++) {
                float4 t4 = *(const float4*)&gb[g * 1024 + nb + 4 * j0];
                pv[g * 4 + 0] = t4.x; pv[g * 4 + 1] = t4.y;
                pv[g * 4 + 2] = t4.z; pv[g * 4 + 3] = t4.w;
            }
        }
    };
    pfetch(0);

    for (int s = 0; s < NSTEP; s++) {
        const bool wload = (s == 0) || (s == SS) || (s == SS + 1);
        const __half* Wsrc = ((s < SS) ? WtE : ((s == SS) ? WtD : WtF))
                             + (size_t)nt * 69632;
        const __half* Asrc = hT16 + (size_t)((s & 1) * 2 + mt) * 73728;
        __half* Adst = hT16 + (size_t)(((s + 1) & 1) * 2 + mt) * 73728;

        auto issue = [&](int c) {
            int st = c & 1;
            unsigned tx = 18432u + (wload ? 17408u : 0u);
            mbar_expect(barb + st * 8, tx);
            bulk_g2s(sb + (unsigned)(st * 18432), Asrc + (size_t)c * 9216,
                     18432, barb + st * 8);
            if (wload)
                bulk_g2s(sb + RS_W + (unsigned)c * 17408, Wsrc + (size_t)c * 8704,
                         17408, barb + st * 8);
        };

        if (tid == 0) { issue(0); issue(1); }

        wmma::fragment<wmma::accumulator, 16, 16, 16, float> acc[2][2];
        #pragma unroll
        for (int i = 0; i < 2; i++)
            #pragma unroll
            for (int q = 0; q < 2; q++) wmma::fill_fragment(acc[i][q], 0.f);

        for (int c = 0; c < 8; c++) {
            int st = c & 1;
            mbar_wait(barb + st * 8, (c >> 1) & 1);
            const __half* A = sA + st * 9216;           // [k128][72m]
            const __half* Wc = sW + (size_t)c * 8704;   // [64r][136k]
            #pragma unroll
            for (int kk = 0; kk < 4; kk++) {
                int k0 = wk * 64 + kk * 16;
                wmma::fragment<wmma::matrix_a, 16, 16, 16, __half, wmma::col_major> a0, a1;
                wmma::fragment<wmma::matrix_b, 16, 16, 16, __half, wmma::col_major> b0, b1;
                wmma::load_matrix_sync(a0, &A[(size_t)k0 * 72 + wm * 32], 72);
                wmma::load_matrix_sync(a1, &A[(size_t)k0 * 72 + wm * 32 + 16], 72);
                wmma::load_matrix_sync(b0, &Wc[(size_t)(wn * 32) * 136 + k0], 136);
                wmma::load_matrix_sync(b1, &Wc[(size_t)(wn * 32 + 16) * 136 + k0], 136);
                wmma::mma_sync(acc[0][0], a0, b0, acc[0][0]);
                wmma::mma_sync(acc[0][1], a0, b1, acc[0][1]);
                wmma::mma_sync(acc[1][0], a1, b0, acc[1][0]);
                wmma::mma_sync(acc[1][1], a1, b1, acc[1][1]);
            }
            __syncthreads();
            if (tid == 0 && c + 2 < 8) issue(c + 2);
        }

        float* sCd = (wk == 0) ? sC0 : sC1;
        #pragma unroll
        for (int i = 0; i < 2; i++)
            #pragma unroll
            for (int q = 0; q < 2; q++)
                wmma::store_matrix_sync(&sCd[(wm * 32 + i * 16) * 68 + wn * 32 + q * 16],
                                        acc[i][q], 68, wmma::mem_row_major);
        __syncthreads();

        // pointwise: thread (mloc, j0) owns j = 4*j0 + jj (matches float4 P layout)
        #pragma unroll
        for (int jj = 0; jj < 4; jj++) {
            int j = 4 * j0 + jj;
            int n = nb + j;
            float Gi = sC0[mloc * 68 + j]      + sC1[mloc * 68 + j]      + pv[jj];
            float Gf = sC0[mloc * 68 + 16 + j] + sC1[mloc * 68 + 16 + j] + pv[4 + jj];
            float Gg = sC0[mloc * 68 + 32 + j] + sC1[mloc * 68 + 32 + j] + pv[8 + jj];
            float Go = sC0[mloc * 68 + 48 + j] + sC1[mloc * 68 + 48 + j] + pv[12 + jj];
            float si = 1.f / (1.f + __expf(-Gi));
            float sf = 1.f / (1.f + __expf(-Gf));
            float so = 1.f / (1.f + __expf(-Go));
            float tg = __fdividef(2.f, 1.f + __expf(-2.f * Gg)) - 1.f;
            float cn = sf * cst[jj] + si * tg;
            cst[jj] = cn;
            float tc = __fdividef(2.f, 1.f + __expf(-2.f * cn)) - 1.f;
            float hn = so * tc;
            Adst[((size_t)(n >> 7) * 128 + (n & 127)) * 72 + mloc] = __float2half(hn);
            if (s >= SS) {
                int t = s - SS;
                Hall16[(((size_t)t * 8 + (n >> 7)) * 128 + mt * 64 + mloc) * 136 + (n & 127)]
                    = __float2half(hn);
            }
        }

        // prefetch next step's P/bias NOW — latency hides behind the barrier + MMAs
        if (s + 1 < NSTEP) pfetch(s + 1);

        if (s < NSTEP - 1) gridbar2(mt, epoch);
    }
}

// ---------------- host launch ----------------
extern "C" void kernel_launch(void* const* d_in, const int* in_sizes, int n_in,
                              void* d_out, int out_size) {
    int wbase = (n_in >= 12 && in_sizes[1] == 1) ? 2 : 1;

    const float* x     = (const float*)d_in[0];
    const float* Wih_e = (const float*)d_in[wbase + 0];
    const float* Whh_e = (const float*)d_in[wbase + 1];
    const float* bih_e = (const float*)d_in[wbase + 2];
    const float* bhh_e = (const float*)d_in[wbase + 3];
    const float* Wih_d = (const float*)d_in[wbase + 4];
    const float* Whh_d = (const float*)d_in[wbase + 5];
    const float* bih_d = (const float*)d_in[wbase + 6];
    const float* bhh_d = (const float*)d_in[wbase + 7];
    const float* Wproj = (const float*)d_in[wbase + 8];
    const float* bproj = (const float*)d_in[wbase + 9];
    float* out = (float*)d_out;

    float *Ppk, *WihDpk, *WpTpk, *benc, *bdec, *beff;
    __half *xpk16, *WihE16, *Wproj16, *Hall16, *WtE, *WtD, *WtF, *hT16;
    cudaGetSymbolAddress((void**)&Ppk,     g_Ppk);
    cudaGetSymbolAddress((void**)&xpk16,   g_xpk16);
    cudaGetSymbolAddress((void**)&WihE16,  g_WihE16);
    cudaGetSymbolAddress((void**)&Wproj16, g_Wproj16);
    cudaGetSymbolAddress((void**)&Hall16,  g_Hall16);
    cudaGetSymbolAddress((void**)&WihDpk,  g_WihDpk);
    cudaGetSymbolAddress((void**)&WpTpk,   g_WpTpk);
    cudaGetSymbolAddress((void**)&WtE,     g_Wt16E);
    cudaGetSymbolAddress((void**)&WtD,     g_Wt16D);
    cudaGetSymbolAddress((void**)&WtF,     g_Wt16F);
    cudaGetSymbolAddress((void**)&hT16,    g_hT16);
    cudaGetSymbolAddress((void**)&benc,    g_benc);
    cudaGetSymbolAddress((void**)&bdec,    g_bdec);
    cudaGetSymbolAddress((void**)&beff,    g_beff);

    const int gemmSmemB = 4 * GA * 4 + 64;
    const int gemmSmemH = 4 * HA * 2 + 64;
    cudaFuncSetAttribute(k_gemmB, cudaFuncAttributeMaxDynamicSharedMemorySize, gemmSmemB);
    cudaFuncSetAttribute(k_gemmH, cudaFuncAttributeMaxDynamicSharedMemorySize, gemmSmemH);
    cudaFuncSetAttribute(k_rec16, cudaFuncAttributeMaxDynamicSharedMemorySize, RS_SMEM);

    // biases
    k_vec_add<<<16, 256>>>(bih_e, bhh_e, benc, G4H);
    k_vec_add<<<16, 256>>>(bih_d, bhh_d, bdec, G4H);
    k_beff<<<16, 256>>>(Wih_d, bproj, bdec, beff);

    // fp16 packs (P + final GEMM operands)
    k_pack16<<<(int)(((size_t)BB * SS * II / 4 + 255) / 256), 256>>>(
        x, xpk16, II, (size_t)BB * SS * II);
    k_pack16<<<(int)(((size_t)G4H * II / 4 + 255) / 256), 256>>>(
        Wih_e, WihE16, II, (size_t)G4H * II);
    k_pack16<<<(int)(((size_t)OO * HH / 4 + 255) / 256), 256>>>(
        Wproj, Wproj16, HH, (size_t)OO * HH);
    // tf32 packs (Weff GEMM operands)
    k_pack<<<(int)(((size_t)G4H * OO / 4 + 255) / 256), 256>>>(
        Wih_d, WihDpk, OO, (size_t)G4H * OO);
    k_pack_T<<<(HH * OO + 255) / 256, 256>>>(Wproj, WpTpk);
    // rec weight images
    k_pack_w16<<<(64 * 8 * 64 * 128) / 256, 256>>>(Whh_e, WtE);
    k_pack_w16<<<(64 * 8 * 64 * 128) / 256, 256>>>(Whh_d, WtD);

    // W_eff = W_ih_dec @ W_proj + W_hh_dec -> fp16 rec image (tf32 GEMM, mode 3)
    k_gemmB<<<dim3(HH / 128, G4H / 128), 256, gemmSmemB>>>(
        WihDpk, WpTpk, (float*)WtF, HH, OO, nullptr, Whh_d, 3);

    // P = X @ W_ih_enc^T + b_enc -> Ppk (fp16 GEMM, mode 1, coalesced store)
    k_gemmH<<<dim3(G4H / 128, (BB * SS) / 128), 256, gemmSmemH>>>(
        xpk16, WihE16, Ppk, II, benc, 1);

    // zero h images, reset barriers, run the 384-step recurrence
    k_zero<<<(2 * 2 * 8 * 128 * 72 / 2 + 255) / 256, 256>>>((float*)hT16,
                                                            2 * 2 * 8 * 128 * 72 / 2);
    k_reset_bar<<<1, 1>>>();
    k_rec16<<<NCTA_REC, 256, RS_SMEM>>>(Ppk, WtE, WtD, WtF, bdec, beff, hT16, Hall16);

    // Y = Hall @ W_proj^T + b_proj -> out[b][t][o] (fp16 GEMM, mode 2)
    k_gemmH<<<dim3(OO / 128, (BB * TT) / 128), 256, gemmSmemH>>>(
        Hall16, Wproj16, out, HH, bproj, 2);
}

// round 15
// speedup vs baseline: 1.0636x; 1.0079x over previous
#include <cuda_runtime.h>
#include <cuda_fp16.h>
#include <mma.h>
#include <math.h>

using namespace nvcuda;

#define BB  128
#define SS  256
#define II  512
#define HH  1024
#define OO  512
#define TT  128
#define G4H 4096
#define NSTEP (SS + TT)
#define NCTA_REC 128
#define GA 8704            // floats per packed 128x68 K-chunk tile (tf32 GEMM)
#define HA 17408           // halves per packed 128x136 K-chunk tile (fp16 GEMM)

// ---------------- static device scratch ----------------
__device__ __align__(128) float g_Ppk[(size_t)SS * 128 * 4096];   // P [s][cta][m64][col64]
__device__ __align__(128) __half g_xpk16[(size_t)256 * 4 * HA];
__device__ __align__(128) __half g_WihE16[(size_t)32 * 4 * HA];
__device__ __align__(128) __half g_Wproj16[(size_t)4 * 8 * HA];
__device__ __align__(128) __half g_Hall16[(size_t)128 * 8 * HA];  // decoder h fp16 packed
__device__ __align__(128) float g_WihDpk[(size_t)32 * 8 * GA];    // tf32 packs (Weff GEMM)
__device__ __align__(128) float g_WpTpk[(size_t)8 * 8 * GA];
__device__ __align__(128) __half g_Wt16E[(size_t)64 * 8 * 8704];  // rec W images [nt][ch][64r][136k]
__device__ __align__(128) __half g_Wt16D[(size_t)64 * 8 * 8704];
__device__ __align__(128) __half g_Wt16F[(size_t)64 * 8 * 8704];
__device__ __align__(128) __half g_hT16[2 * 2 * 8 * 128 * 72];    // [buf][mt][ch][128k][72m]
__device__ float g_benc[G4H];
__device__ float g_bdec[G4H];
__device__ float g_beff[G4H];
__device__ __align__(128) unsigned g_flags[2][64][32];            // 128B-padded barrier slots

// ---------------- helpers ----------------
__device__ __forceinline__ float tf32t(float x) {
    unsigned u;
    asm("cvt.rna.tf32.f32 %0, %1;" : "=r"(u) : "f"(x));
    return __uint_as_float(u);
}
__device__ __forceinline__ void mbar_init(unsigned mbar, unsigned cnt) {
    asm volatile("mbarrier.init.shared.b64 [%0], %1;" :: "r"(mbar), "r"(cnt) : "memory");
}
__device__ __forceinline__ void mbar_expect(unsigned mbar, unsigned bytes) {
    asm volatile("mbarrier.arrive.expect_tx.shared.b64 _, [%0], %1;"
                 :: "r"(mbar), "r"(bytes) : "memory");
}
__device__ __forceinline__ void mbar_wait(unsigned mbar, unsigned parity) {
    unsigned done = 0;
    while (!done) {
        asm volatile(
            "{\n\t.reg .pred p;\n\t"
            "mbarrier.try_wait.parity.acquire.cta.shared::cta.b64 p, [%1], %2, 0x989680;\n\t"
            "selp.b32 %0, 1, 0, p;\n\t}"
            : "=r"(done) : "r"(mbar), "r"(parity) : "memory");
    }
}
__device__ __forceinline__ void bulk_g2s(unsigned dst, const void* src, unsigned bytes,
                                         unsigned mbar) {
    asm volatile(
        "cp.async.bulk.shared::cluster.global.mbarrier::complete_tx::bytes [%0], [%1], %2, [%3];"
        :: "r"(dst), "l"(src), "r"(bytes), "r"(mbar) : "memory");
}

// ---------------- flag-array grid barrier (per-mt groups of 64 CTAs) ----------------
// One parallel STG per CTA into its own 128B slot; 64 pollers; no atomic serialization.
__device__ __forceinline__ void gridbarF(int mt, int nt, int& epoch) {
    epoch++;
    __threadfence();
    __syncthreads();
    if (threadIdx.x == 0)
        *(volatile unsigned*)&g_flags[mt][nt][0] = (unsigned)epoch;
    if (threadIdx.x < 64) {
        volatile unsigned* p = &g_flags[mt][threadIdx.x][0];
        while (*p < (unsigned)epoch) { }
    }
    __syncthreads();
}
__global__ void k_reset_bar() {
    if (threadIdx.x < 128) g_flags[threadIdx.x >> 6][threadIdx.x & 63][0] = 0u;
}

// ---------------- small kernels ----------------
__global__ void k_zero(float* p, int n) {
    int i = blockIdx.x * blockDim.x + threadIdx.x;
    if (i < n) p[i] = 0.f;
}
__global__ void k_vec_add(const float* __restrict__ a, const float* __restrict__ b,
                          float* __restrict__ o, int n) {
    int i = blockIdx.x * blockDim.x + threadIdx.x;
    if (i < n) o[i] = a[i] + b[i];
}
__global__ void k_beff(const float* __restrict__ Wih, const float* __restrict__ bproj,
                       const float* __restrict__ bdec, float* __restrict__ beff) {
    int n = blockIdx.x * blockDim.x + threadIdx.x;
    if (n < G4H) {
        float s = bdec[n];
        const float* wr = Wih + (size_t)n * OO;
        #pragma unroll 8
        for (int o = 0; o < OO; o++) s += wr[o] * bproj[o];
        beff[n] = s;
    }
}
// tf32 pack: src [M][K] -> [mtile][kc64][128][68]
__global__ void k_pack(const float* __restrict__ src, float* __restrict__ dst,
                       int K, size_t total) {
    size_t i = ((size_t)blockIdx.x * 256 + threadIdx.x) * 4;
    if (i < total) {
        int r = (int)(i / (unsigned)K);
        int k = (int)(i - (size_t)r * K);
        float4 v = *(const float4*)&src[i];
        v.x = tf32t(v.x); v.y = tf32t(v.y); v.z = tf32t(v.z); v.w = tf32t(v.w);
        int nk = K >> 6;
        size_t d = ((size_t)(r >> 7) * nk + (k >> 6)) * GA + (r & 127) * 68 + (k & 63);
        *(float4*)&dst[d] = v;
    }
}
// fp16 pack: src [M][K] -> [mtile][kc128][128][136]
__global__ void k_pack16(const float* __restrict__ src, __half* __restrict__ dst,
                         int K, size_t total) {
    size_t i = ((size_t)blockIdx.x * 256 + threadIdx.x) * 4;
    if (i < total) {
        int r = (int)(i / (unsigned)K);
        int k = (int)(i - (size_t)r * K);
        float4 v = *(const float4*)&src[i];
        __half2 h0 = __floats2half2_rn(v.x, v.y);
        __half2 h1 = __floats2half2_rn(v.z, v.w);
        int nk = K >> 7;
        size_t d = ((size_t)(r >> 7) * nk + (k >> 7)) * HA + (r & 127) * 136 + (k & 127);
        *(__half2*)&dst[d]     = h0;
        *(__half2*)&dst[d + 2] = h1;
    }
}
// pack transpose of Wproj [O][H] as tf32 B operand rows n (N=1024, K=512)
__global__ void k_pack_T(const float* __restrict__ Wproj, float* __restrict__ dst) {
    int i = blockIdx.x * blockDim.x + threadIdx.x;
    if (i < HH * OO) {
        int n = i >> 9, o = i & 511;
        float v = tf32t(Wproj[(size_t)o * HH + n]);
        size_t d = ((size_t)(n >> 7) * 8 + (o >> 6)) * GA + (n & 127) * 68 + (o & 63);
        dst[d] = v;
    }
}
// W [4H][H] fp32 -> fp16 rec image [nt64][ch8][row64][136]
__global__ void k_pack_w16(const float* __restrict__ W, __half* __restrict__ dst) {
    int i = blockIdx.x * blockDim.x + threadIdx.x;
    if (i < 64 * 8 * 64 * 128) {
        int kl = i & 127, r = (i >> 7) & 63, ch = (i >> 13) & 7, nt = i >> 16;
        int gr = (r >> 4) * 1024 + nt * 16 + (r & 15);
        dst[(((size_t)nt * 8 + ch) * 64 + r) * 136 + kl] =
            __float2half(W[(size_t)gr * HH + ch * 128 + kl]);
    }
}

// ---------------- tf32 GEMM (Weff only, mode 3) ----------------
__global__ void __launch_bounds__(256) k_gemmB(
        const float* __restrict__ Apk, const float* __restrict__ Bpk,
        float* __restrict__ C, int ldc, int K,
        const float* __restrict__ bias, const float* __restrict__ addm, int mode) {
    extern __shared__ float sm[];
    unsigned sbase = (unsigned)__cvta_generic_to_shared(sm);
    unsigned barb  = sbase + 4 * GA * 4;
    const int tid = threadIdx.x;
    const int m0 = blockIdx.y * 128, n0 = blockIdx.x * 128;
    const int w = tid >> 5, wm = w >> 1, wn = w & 1;
    const int nKc = K >> 6;

    if (tid < 2) mbar_init(barb + tid * 8, 1);
    __syncthreads();

    auto issue = [&](int i) {
        if (tid == 0) {
            int st = i & 1;
            mbar_expect(barb + st * 8, 2 * GA * 4);
            bulk_g2s(sbase + (unsigned)(st * GA) * 4,
                     Apk + ((size_t)blockIdx.y * nKc + i) * GA, GA * 4, barb + st * 8);
            bulk_g2s(sbase + (unsigned)((2 + st) * GA) * 4,
                     Bpk + ((size_t)blockIdx.x * nKc + i) * GA, GA * 4, barb + st * 8);
        }
    };

    wmma::fragment<wmma::accumulator, 16, 16, 8, float> acc[2][4];
    #pragma unroll
    for (int i = 0; i < 2; i++)
        #pragma unroll
        for (int j = 0; j < 4; j++) wmma::fill_fragment(acc[i][j], 0.f);

    issue(0);
    if (nKc > 1) issue(1);

    for (int it = 0; it < nKc; it++) {
        int st = it & 1;
        mbar_wait(barb + st * 8, (it >> 1) & 1);
        const float* a = sm + st * GA;
        const float* b = sm + (2 + st) * GA;
        #pragma unroll
        for (int kk = 0; kk < 8; kk++) {
            wmma::fragment<wmma::matrix_a, 16, 16, 8, wmma::precision::tf32, wmma::row_major> a0, a1;
            wmma::fragment<wmma::matrix_b, 16, 16, 8, wmma::precision::tf32, wmma::col_major> bf[4];
            wmma::load_matrix_sync(a0, &a[(wm * 32) * 68 + kk * 8], 68);
            wmma::load_matrix_sync(a1, &a[(wm * 32 + 16) * 68 + kk * 8], 68);
            #pragma unroll
            for (int t = 0; t < 4; t++)
                wmma::load_matrix_sync(bf[t], &b[(wn * 64 + t * 16) * 68 + kk * 8], 68);
            #pragma unroll
            for (int t = 0; t < 4; t++) {
                wmma::mma_sync(acc[0][t], a0, bf[t], acc[0][t]);
                wmma::mma_sync(acc[1][t], a1, bf[t], acc[1][t]);
            }
        }
        __syncthreads();
        if (it + 2 < nKc) issue(it + 2);
    }

    float* sC = sm;
    #pragma unroll
    for (int i = 0; i < 2; i++)
        #pragma unroll
        for (int t = 0; t < 4; t++)
            wmma::store_matrix_sync(&sC[(wm * 32 + i * 16) * 132 + wn * 64 + t * 16],
                                    acc[i][t], 132, wmma::mem_row_major);
    __syncthreads();

    for (int idx = tid; idx < 128 * 128; idx += 256) {
        int m = idx >> 7, n = idx & 127;
        float v = sC[m * 132 + n];
        if (bias) v += bias[n0 + n];
        {   // mode 3: Weff -> fp16 rec image (+Whh_d)
            int gr = m0 + m, k = n0 + n;
            v += addm[(size_t)gr * ldc + k];
            int g = gr >> 10, cc = gr & 1023, nt2 = cc >> 4, r = g * 16 + (cc & 15);
            ((__half*)C)[(((size_t)nt2 * 8 + (k >> 7)) * 64 + r) * 136 + (k & 127)] =
                __float2half(v);
        }
    }
}

// ---------------- fp16 GEMM on packed operands ----------------
// C = A * B^T. mode 1: P store (+bias), coalesced [s][cta][m][col]. mode 2: final out remap (+bias).
__global__ void __launch_bounds__(256) k_gemmH(
        const __half* __restrict__ Apk, const __half* __restrict__ Bpk,
        float* __restrict__ C, int K,
        const float* __restrict__ bias, int mode) {
    extern __shared__ char smh[];
    __half* sm = (__half*)smh;
    unsigned sbase = (unsigned)__cvta_generic_to_shared(smh);
    unsigned barb  = sbase + 4 * HA * 2;
    const int tid = threadIdx.x;
    const int m0 = blockIdx.y * 128, n0 = blockIdx.x * 128;
    const int w = tid >> 5, wm = w >> 1, wn = w & 1;
    const int nKc = K >> 7;

    if (tid < 2) mbar_init(barb + tid * 8, 1);
    __syncthreads();

    auto issue = [&](int i) {
        if (tid == 0) {
            int st = i & 1;
            mbar_expect(barb + st * 8, 2 * HA * 2);
            bulk_g2s(sbase + (unsigned)(st * HA) * 2,
                     Apk + ((size_t)blockIdx.y * nKc + i) * HA, HA * 2, barb + st * 8);
            bulk_g2s(sbase + (unsigned)((2 + st) * HA) * 2,
                     Bpk + ((size_t)blockIdx.x * nKc + i) * HA, HA * 2, barb + st * 8);
        }
    };

    wmma::fragment<wmma::accumulator, 16, 16, 16, float> acc[2][4];
    #pragma unroll
    for (int i = 0; i < 2; i++)
        #pragma unroll
        for (int j = 0; j < 4; j++) wmma::fill_fragment(acc[i][j], 0.f);

    issue(0);
    if (nKc > 1) issue(1);

    for (int it = 0; it < nKc; it++) {
        int st = it & 1;
        mbar_wait(barb + st * 8, (it >> 1) & 1);
        const __half* a = sm + st * HA;
        const __half* b = sm + (2 + st) * HA;
        #pragma unroll
        for (int kk = 0; kk < 8; kk++) {
            wmma::fragment<wmma::matrix_a, 16, 16, 16, __half, wmma::row_major> a0, a1;
            wmma::fragment<wmma::matrix_b, 16, 16, 16, __half, wmma::col_major> bf[4];
            wmma::load_matrix_sync(a0, &a[(size_t)(wm * 32) * 136 + kk * 16], 136);
            wmma::load_matrix_sync(a1, &a[(size_t)(wm * 32 + 16) * 136 + kk * 16], 136);
            #pragma unroll
            for (int t = 0; t < 4; t++)
                wmma::load_matrix_sync(bf[t], &b[(size_t)(wn * 64 + t * 16) * 136 + kk * 16], 136);
            #pragma unroll
            for (int t = 0; t < 4; t++) {
                wmma::mma_sync(acc[0][t], a0, bf[t], acc[0][t]);
                wmma::mma_sync(acc[1][t], a1, bf[t], acc[1][t]);
            }
        }
        __syncthreads();
        if (it + 2 < nKc) issue(it + 2);
    }

    float* sC = (float*)smh;
    #pragma unroll
    for (int i = 0; i < 2; i++)
        #pragma unroll
        for (int t = 0; t < 4; t++)
            wmma::store_matrix_sync(&sC[(wm * 32 + i * 16) * 132 + wn * 64 + t * 16],
                                    acc[i][t], 132, wmma::mem_row_major);
    __syncthreads();

    for (int idx = tid; idx < 128 * 128; idx += 256) {
        int n = idx & 127, m = idx >> 7;          // n-minor: coalesced stores
        float v = sC[m * 132 + n];
        if (bias) v += bias[n0 + n];
        if (mode == 1) {            // P: GEMM row r = b*256+s -> Ppk[s][cta][m][col]
            int r = m0 + m, ng = n0 + n;
            int bb = r >> 8, s = r & 255;
            int g = ng >> 10, cc = ng & 1023, nt2 = cc >> 4, j = cc & 15;
            int cta = 2 * nt2 + (bb >> 6);
            C[(((size_t)s * 128 + cta) * 64 + (bb & 63)) * 64 + g * 16 + j] = v;
        } else {                    // final: r = t*128+b -> out[b][t][n]
            int r = m0 + m; int b = r & 127, t = r >> 7;
            C[((size_t)b * TT + t) * OO + n0 + n] = v;
        }
    }
}

// ---------------- persistent fp16 recurrence (R12 body, flag barrier) ----------------
// smem bytes: A 2x18432 @0 | Wres 8x17408 @36864 | sC0 @176128 | sC1 @193536 | bars @210944
#define RS_W    36864u
#define RS_C0   176128u
#define RS_C1   193536u
#define RS_BAR  210944u
#define RS_SMEM 210960

__global__ void __launch_bounds__(256, 1) k_rec16(
        const float* __restrict__ Ppk,
        const __half* __restrict__ WtE,
        const __half* __restrict__ WtD,
        const __half* __restrict__ WtF,
        const float* __restrict__ bdec,
        const float* __restrict__ beff,
        __half* __restrict__ hT16,
        __half* __restrict__ Hall16) {
    extern __shared__ __align__(128) char smc[];
    __half* sA = (__half*)smc;
    __half* sW = (__half*)(smc + RS_W);
    float* sC0 = (float*)(smc + RS_C0);
    float* sC1 = (float*)(smc + RS_C1);
    unsigned sb   = (unsigned)__cvta_generic_to_shared(smc);
    unsigned barb = sb + RS_BAR;

    const int tid = threadIdx.x, cta = blockIdx.x;
    const int mt = cta & 1, nt = cta >> 1, nb = nt * 16;
    const int w = tid >> 5;
    const int wm = w & 1, wn = (w >> 1) & 1, wk = w >> 2;
    const int mloc = tid & 63, j0 = tid >> 6;

    if (tid < 2) mbar_init(barb + tid * 8, 1);
    __syncthreads();

    float cst[4];
    #pragma unroll
    for (int jj = 0; jj < 4; jj++) cst[jj] = 0.f;

    int epoch = 0;

    for (int s = 0; s < NSTEP; s++) {
        const bool wload = (s == 0) || (s == SS) || (s == SS + 1);
        const __half* Wsrc = ((s < SS) ? WtE : ((s == SS) ? WtD : WtF))
                             + (size_t)nt * 69632;
        const __half* Asrc = hT16 + (size_t)((s & 1) * 2 + mt) * 73728;
        __half* Adst = hT16 + (size_t)(((s + 1) & 1) * 2 + mt) * 73728;

        auto issue = [&](int c) {
            int st = c & 1;
            unsigned tx = 18432u + (wload ? 17408u : 0u);
            mbar_expect(barb + st * 8, tx);
            bulk_g2s(sb + (unsigned)(st * 18432), Asrc + (size_t)c * 9216,
                     18432, barb + st * 8);
            if (wload)
                bulk_g2s(sb + RS_W + (unsigned)c * 17408, Wsrc + (size_t)c * 8704,
                         17408, barb + st * 8);
        };

        if (tid == 0) { issue(0); issue(1); }

        // prefetch P / bias into registers: 4x float4 per thread (hidden behind MMAs)
        float pv[16];
        if (s < SS) {
            const float* Ps = Ppk + ((size_t)s * 128 + cta) * 4096 + mloc * 64 + 4 * j0;
            #pragma unroll
            for (int g = 0; g < 4; g++) {
                float4 t4 = *(const float4*)&Ps[g * 16];
                pv[g * 4 + 0] = t4.x; pv[g * 4 + 1] = t4.y;
                pv[g * 4 + 2] = t4.z; pv[g * 4 + 3] = t4.w;
            }
        } else {
            const float* gb = (s == SS) ? bdec : beff;
            #pragma unroll
            for (int g = 0; g < 4; g++) {
                float4 t4 = *(const float4*)&gb[g * 1024 + nb + 4 * j0];
                pv[g * 4 + 0] = t4.x; pv[g * 4 + 1] = t4.y;
                pv[g * 4 + 2] = t4.z; pv[g * 4 + 3] = t4.w;
            }
        }

        wmma::fragment<wmma::accumulator, 16, 16, 16, float> acc[2][2];
        #pragma unroll
        for (int i = 0; i < 2; i++)
            #pragma unroll
            for (int q = 0; q < 2; q++) wmma::fill_fragment(acc[i][q], 0.f);

        for (int c = 0; c < 8; c++) {
            int st = c & 1;
            mbar_wait(barb + st * 8, (c >> 1) & 1);
            const __half* A = sA + st * 9216;           // [k128][72m]
            const __half* Wc = sW + (size_t)c * 8704;   // [64r][136k]
            #pragma unroll
            for (int kk = 0; kk < 4; kk++) {
                int k0 = wk * 64 + kk * 16;
                wmma::fragment<wmma::matrix_a, 16, 16, 16, __half, wmma::col_major> a0, a1;
                wmma::fragment<wmma::matrix_b, 16, 16, 16, __half, wmma::col_major> b0, b1;
                wmma::load_matrix_sync(a0, &A[(size_t)k0 * 72 + wm * 32], 72);
                wmma::load_matrix_sync(a1, &A[(size_t)k0 * 72 + wm * 32 + 16], 72);
                wmma::load_matrix_sync(b0, &Wc[(size_t)(wn * 32) * 136 + k0], 136);
                wmma::load_matrix_sync(b1, &Wc[(size_t)(wn * 32 + 16) * 136 + k0], 136);
                wmma::mma_sync(acc[0][0], a0, b0, acc[0][0]);
                wmma::mma_sync(acc[0][1], a0, b1, acc[0][1]);
                wmma::mma_sync(acc[1][0], a1, b0, acc[1][0]);
                wmma::mma_sync(acc[1][1], a1, b1, acc[1][1]);
            }
            __syncthreads();
            if (tid == 0 && c + 2 < 8) issue(c + 2);
        }

        float* sCd = (wk == 0) ? sC0 : sC1;
        #pragma unroll
        for (int i = 0; i < 2; i++)
            #pragma unroll
            for (int q = 0; q < 2; q++)
                wmma::store_matrix_sync(&sCd[(wm * 32 + i * 16) * 68 + wn * 32 + q * 16],
                                        acc[i][q], 68, wmma::mem_row_major);
        __syncthreads();

        // pointwise: thread (mloc, j0) owns j = 4*j0 + jj (matches float4 P layout)
        #pragma unroll
        for (int jj = 0; jj < 4; jj++) {
            int j = 4 * j0 + jj;
            int n = nb + j;
            float Gi = sC0[mloc * 68 + j]      + sC1[mloc * 68 + j]      + pv[jj];
            float Gf = sC0[mloc * 68 + 16 + j] + sC1[mloc * 68 + 16 + j] + pv[4 + jj];
            float Gg = sC0[mloc * 68 + 32 + j] + sC1[mloc * 68 + 32 + j] + pv[8 + jj];
            float Go = sC0[mloc * 68 + 48 + j] + sC1[mloc * 68 + 48 + j] + pv[12 + jj];
            float si = 1.f / (1.f + __expf(-Gi));
            float sf = 1.f / (1.f + __expf(-Gf));
            float so = 1.f / (1.f + __expf(-Go));
            float tg = __fdividef(2.f, 1.f + __expf(-2.f * Gg)) - 1.f;
            float cn = sf * cst[jj] + si * tg;
            cst[jj] = cn;
            float tc = __fdividef(2.f, 1.f + __expf(-2.f * cn)) - 1.f;
            float hn = so * tc;
            Adst[((size_t)(n >> 7) * 128 + (n & 127)) * 72 + mloc] = __float2half(hn);
            if (s >= SS) {
                int t = s - SS;
                Hall16[(((size_t)t * 8 + (n >> 7)) * 128 + mt * 64 + mloc) * 136 + (n & 127)]
                    = __float2half(hn);
            }
        }

        if (s < NSTEP - 1) gridbarF(mt, nt, epoch);
    }
}

// ---------------- host launch ----------------
extern "C" void kernel_launch(void* const* d_in, const int* in_sizes, int n_in,
                              void* d_out, int out_size) {
    int wbase = (n_in >= 12 && in_sizes[1] == 1) ? 2 : 1;

    const float* x     = (const float*)d_in[0];
    const float* Wih_e = (const float*)d_in[wbase + 0];
    const float* Whh_e = (const float*)d_in[wbase + 1];
    const float* bih_e = (const float*)d_in[wbase + 2];
    const float* bhh_e = (const float*)d_in[wbase + 3];
    const float* Wih_d = (const float*)d_in[wbase + 4];
    const float* Whh_d = (const float*)d_in[wbase + 5];
    const float* bih_d = (const float*)d_in[wbase + 6];
    const float* bhh_d = (const float*)d_in[wbase + 7];
    const float* Wproj = (const float*)d_in[wbase + 8];
    const float* bproj = (const float*)d_in[wbase + 9];
    float* out = (float*)d_out;

    float *Ppk, *WihDpk, *WpTpk, *benc, *bdec, *beff;
    __half *xpk16, *WihE16, *Wproj16, *Hall16, *WtE, *WtD, *WtF, *hT16;
    cudaGetSymbolAddress((void**)&Ppk,     g_Ppk);
    cudaGetSymbolAddress((void**)&xpk16,   g_xpk16);
    cudaGetSymbolAddress((void**)&WihE16,  g_WihE16);
    cudaGetSymbolAddress((void**)&Wproj16, g_Wproj16);
    cudaGetSymbolAddress((void**)&Hall16,  g_Hall16);
    cudaGetSymbolAddress((void**)&WihDpk,  g_WihDpk);
    cudaGetSymbolAddress((void**)&WpTpk,   g_WpTpk);
    cudaGetSymbolAddress((void**)&WtE,     g_Wt16E);
    cudaGetSymbolAddress((void**)&WtD,     g_Wt16D);
    cudaGetSymbolAddress((void**)&WtF,     g_Wt16F);
    cudaGetSymbolAddress((void**)&hT16,    g_hT16);
    cudaGetSymbolAddress((void**)&benc,    g_benc);
    cudaGetSymbolAddress((void**)&bdec,    g_bdec);
    cudaGetSymbolAddress((void**)&beff,    g_beff);

    const int gemmSmemB = 4 * GA * 4 + 64;
    const int gemmSmemH = 4 * HA * 2 + 64;
    cudaFuncSetAttribute(k_gemmB, cudaFuncAttributeMaxDynamicSharedMemorySize, gemmSmemB);
    cudaFuncSetAttribute(k_gemmH, cudaFuncAttributeMaxDynamicSharedMemorySize, gemmSmemH);
    cudaFuncSetAttribute(k_rec16, cudaFuncAttributeMaxDynamicSharedMemorySize, RS_SMEM);

    // biases
    k_vec_add<<<16, 256>>>(bih_e, bhh_e, benc, G4H);
    k_vec_add<<<16, 256>>>(bih_d, bhh_d, bdec, G4H);
    k_beff<<<16, 256>>>(Wih_d, bproj, bdec, beff);

    // fp16 packs (P + final GEMM operands)
    k_pack16<<<(int)(((size_t)BB * SS * II / 4 + 255) / 256), 256>>>(
        x, xpk16, II, (size_t)BB * SS * II);
    k_pack16<<<(int)(((size_t)G4H * II / 4 + 255) / 256), 256>>>(
        Wih_e, WihE16, II, (size_t)G4H * II);
    k_pack16<<<(int)(((size_t)OO * HH / 4 + 255) / 256), 256>>>(
        Wproj, Wproj16, HH, (size_t)OO * HH);
    // tf32 packs (Weff GEMM operands)
    k_pack<<<(int)(((size_t)G4H * OO / 4 + 255) / 256), 256>>>(
        Wih_d, WihDpk, OO, (size_t)G4H * OO);
    k_pack_T<<<(HH * OO + 255) / 256, 256>>>(Wproj, WpTpk);
    // rec weight images
    k_pack_w16<<<(64 * 8 * 64 * 128) / 256, 256>>>(Whh_e, WtE);
    k_pack_w16<<<(64 * 8 * 64 * 128) / 256, 256>>>(Whh_d, WtD);

    // W_eff = W_ih_dec @ W_proj + W_hh_dec -> fp16 rec image (tf32 GEMM, mode 3)
    k_gemmB<<<dim3(HH / 128, G4H / 128), 256, gemmSmemB>>>(
        WihDpk, WpTpk, (float*)WtF, HH, OO, nullptr, Whh_d, 3);

    // P = X @ W_ih_enc^T + b_enc -> Ppk (fp16 GEMM, mode 1, coalesced store)
    k_gemmH<<<dim3(G4H / 128, (BB * SS) / 128), 256, gemmSmemH>>>(
        xpk16, WihE16, Ppk, II, benc, 1);

    // zero h images, reset barrier flags, run the 384-step recurrence
    k_zero<<<(2 * 2 * 8 * 128 * 72 / 2 + 255) / 256, 256>>>((float*)hT16,
                                                            2 * 2 * 8 * 128 * 72 / 2);
    k_reset_bar<<<1, 128>>>();
    k_rec16<<<NCTA_REC, 256, RS_SMEM>>>(Ppk, WtE, WtD, WtF, bdec, beff, hT16, Hall16);

    // Y = Hall @ W_proj^T + b_proj -> out[b][t][o] (fp16 GEMM, mode 2)
    k_gemmH<<<dim3(OO / 128, (BB * TT) / 128), 256, gemmSmemH>>>(
        Hall16, Wproj16, out, HH, bproj, 2);
}

// round 16
// speedup vs baseline: 1.0985x; 1.0328x over previous
#include <cuda_runtime.h>
#include <cuda_fp16.h>
#include <mma.h>
#include <math.h>

using namespace nvcuda;

#define BB  128
#define SS  256
#define II  512
#define HH  1024
#define OO  512
#define TT  128
#define G4H 4096
#define NSTEP (SS + TT)
#define NCTA_REC 128
#define GA 8704            // floats per packed 128x68 K-chunk tile (tf32 GEMM)
#define HA 17408           // halves per packed 128x136 K-chunk tile (fp16 GEMM)

// ---------------- static device scratch ----------------
__device__ __align__(128) float g_Ppk[(size_t)SS * 128 * 4096];   // P [s][cta][m64][col64]
__device__ __align__(128) __half g_xpk16[(size_t)256 * 4 * HA];
__device__ __align__(128) __half g_WihE16[(size_t)32 * 4 * HA];
__device__ __align__(128) __half g_Wproj16[(size_t)4 * 8 * HA];
__device__ __align__(128) __half g_Hall16[(size_t)128 * 8 * HA];  // decoder h fp16 packed
__device__ __align__(128) float g_WihDpk[(size_t)32 * 8 * GA];    // tf32 packs (Weff GEMM)
__device__ __align__(128) float g_WpTpk[(size_t)8 * 8 * GA];
__device__ __align__(128) __half g_Wt16E[(size_t)64 * 8 * 8704];  // rec W images [nt][ch][64r][136k]
__device__ __align__(128) __half g_Wt16D[(size_t)64 * 8 * 8704];
__device__ __align__(128) __half g_Wt16F[(size_t)64 * 8 * 8704];
__device__ __align__(128) __half g_hT16[2 * 2 * 8 * 128 * 72];    // [buf][mt][ch][128k][72m]
__device__ float g_benc[G4H];
__device__ float g_bdec[G4H];
__device__ float g_beff[G4H];
__device__ unsigned g_bar2[2];

// ---------------- helpers ----------------
__device__ __forceinline__ float tf32t(float x) {
    unsigned u;
    asm("cvt.rna.tf32.f32 %0, %1;" : "=r"(u) : "f"(x));
    return __uint_as_float(u);
}
__device__ __forceinline__ void mbar_init(unsigned mbar, unsigned cnt) {
    asm volatile("mbarrier.init.shared.b64 [%0], %1;" :: "r"(mbar), "r"(cnt) : "memory");
}
__device__ __forceinline__ void mbar_expect(unsigned mbar, unsigned bytes) {
    asm volatile("mbarrier.arrive.expect_tx.shared.b64 _, [%0], %1;"
                 :: "r"(mbar), "r"(bytes) : "memory");
}
__device__ __forceinline__ void mbar_wait(unsigned mbar, unsigned parity) {
    unsigned done = 0;
    while (!done) {
        asm volatile(
            "{\n\t.reg .pred p;\n\t"
            "mbarrier.try_wait.parity.acquire.cta.shared::cta.b64 p, [%1], %2, 0x989680;\n\t"
            "selp.b32 %0, 1, 0, p;\n\t}"
            : "=r"(done) : "r"(mbar), "r"(parity) : "memory");
    }
}
__device__ __forceinline__ void bulk_g2s(unsigned dst, const void* src, unsigned bytes,
                                         unsigned mbar) {
    asm volatile(
        "cp.async.bulk.shared::cluster.global.mbarrier::complete_tx::bytes [%0], [%1], %2, [%3];"
        :: "r"(dst), "l"(src), "r"(bytes), "r"(mbar) : "memory");
}

__global__ void k_reset_bar() { g_bar2[0] = 0u; g_bar2[1] = 0u; }

// ---------------- small kernels ----------------
__global__ void k_zero(float* p, int n) {
    int i = blockIdx.x * blockDim.x + threadIdx.x;
    if (i < n) p[i] = 0.f;
}
__global__ void k_vec_add(const float* __restrict__ a, const float* __restrict__ b,
                          float* __restrict__ o, int n) {
    int i = blockIdx.x * blockDim.x + threadIdx.x;
    if (i < n) o[i] = a[i] + b[i];
}
__global__ void k_beff(const float* __restrict__ Wih, const float* __restrict__ bproj,
                       const float* __restrict__ bdec, float* __restrict__ beff) {
    int n = blockIdx.x * blockDim.x + threadIdx.x;
    if (n < G4H) {
        float s = bdec[n];
        const float* wr = Wih + (size_t)n * OO;
        #pragma unroll 8
        for (int o = 0; o < OO; o++) s += wr[o] * bproj[o];
        beff[n] = s;
    }
}
// tf32 pack: src [M][K] -> [mtile][kc64][128][68]
__global__ void k_pack(const float* __restrict__ src, float* __restrict__ dst,
                       int K, size_t total) {
    size_t i = ((size_t)blockIdx.x * 256 + threadIdx.x) * 4;
    if (i < total) {
        int r = (int)(i / (unsigned)K);
        int k = (int)(i - (size_t)r * K);
        float4 v = *(const float4*)&src[i];
        v.x = tf32t(v.x); v.y = tf32t(v.y); v.z = tf32t(v.z); v.w = tf32t(v.w);
        int nk = K >> 6;
        size_t d = ((size_t)(r >> 7) * nk + (k >> 6)) * GA + (r & 127) * 68 + (k & 63);
        *(float4*)&dst[d] = v;
    }
}
// fp16 pack: src [M][K] -> [mtile][kc128][128][136]
__global__ void k_pack16(const float* __restrict__ src, __half* __restrict__ dst,
                         int K, size_t total) {
    size_t i = ((size_t)blockIdx.x * 256 + threadIdx.x) * 4;
    if (i < total) {
        int r = (int)(i / (unsigned)K);
        int k = (int)(i - (size_t)r * K);
        float4 v = *(const float4*)&src[i];
        __half2 h0 = __floats2half2_rn(v.x, v.y);
        __half2 h1 = __floats2half2_rn(v.z, v.w);
        int nk = K >> 7;
        size_t d = ((size_t)(r >> 7) * nk + (k >> 7)) * HA + (r & 127) * 136 + (k & 127);
        *(__half2*)&dst[d]     = h0;
        *(__half2*)&dst[d + 2] = h1;
    }
}
// pack transpose of Wproj [O][H] as tf32 B operand rows n (N=1024, K=512)
__global__ void k_pack_T(const float* __restrict__ Wproj, float* __restrict__ dst) {
    int i = blockIdx.x * blockDim.x + threadIdx.x;
    if (i < HH * OO) {
        int n = i >> 9, o = i & 511;
        float v = tf32t(Wproj[(size_t)o * HH + n]);
        size_t d = ((size_t)(n >> 7) * 8 + (o >> 6)) * GA + (n & 127) * 68 + (o & 63);
        dst[d] = v;
    }
}
// W [4H][H] fp32 -> fp16 rec image [nt64][ch8][row64][136]
__global__ void k_pack_w16(const float* __restrict__ W, __half* __restrict__ dst) {
    int i = blockIdx.x * blockDim.x + threadIdx.x;
    if (i < 64 * 8 * 64 * 128) {
        int kl = i & 127, r = (i >> 7) & 63, ch = (i >> 13) & 7, nt = i >> 16;
        int gr = (r >> 4) * 1024 + nt * 16 + (r & 15);
        dst[(((size_t)nt * 8 + ch) * 64 + r) * 136 + kl] =
            __float2half(W[(size_t)gr * HH + ch * 128 + kl]);
    }
}

// ---------------- tf32 GEMM (Weff only, mode 3) ----------------
__global__ void __launch_bounds__(256) k_gemmB(
        const float* __restrict__ Apk, const float* __restrict__ Bpk,
        float* __restrict__ C, int ldc, int K,
        const float* __restrict__ bias, const float* __restrict__ addm, int mode) {
    extern __shared__ float sm[];
    unsigned sbase = (unsigned)__cvta_generic_to_shared(sm);
    unsigned barb  = sbase + 4 * GA * 4;
    const int tid = threadIdx.x;
    const int m0 = blockIdx.y * 128, n0 = blockIdx.x * 128;
    const int w = tid >> 5, wm = w >> 1, wn = w & 1;
    const int nKc = K >> 6;

    if (tid < 2) mbar_init(barb + tid * 8, 1);
    __syncthreads();

    auto issue = [&](int i) {
        if (tid == 0) {
            int st = i & 1;
            mbar_expect(barb + st * 8, 2 * GA * 4);
            bulk_g2s(sbase + (unsigned)(st * GA) * 4,
                     Apk + ((size_t)blockIdx.y * nKc + i) * GA, GA * 4, barb + st * 8);
            bulk_g2s(sbase + (unsigned)((2 + st) * GA) * 4,
                     Bpk + ((size_t)blockIdx.x * nKc + i) * GA, GA * 4, barb + st * 8);
        }
    };

    wmma::fragment<wmma::accumulator, 16, 16, 8, float> acc[2][4];
    #pragma unroll
    for (int i = 0; i < 2; i++)
        #pragma unroll
        for (int j = 0; j < 4; j++) wmma::fill_fragment(acc[i][j], 0.f);

    issue(0);
    if (nKc > 1) issue(1);

    for (int it = 0; it < nKc; it++) {
        int st = it & 1;
        mbar_wait(barb + st * 8, (it >> 1) & 1);
        const float* a = sm + st * GA;
        const float* b = sm + (2 + st) * GA;
        #pragma unroll
        for (int kk = 0; kk < 8; kk++) {
            wmma::fragment<wmma::matrix_a, 16, 16, 8, wmma::precision::tf32, wmma::row_major> a0, a1;
            wmma::fragment<wmma::matrix_b, 16, 16, 8, wmma::precision::tf32, wmma::col_major> bf[4];
            wmma::load_matrix_sync(a0, &a[(wm * 32) * 68 + kk * 8], 68);
            wmma::load_matrix_sync(a1, &a[(wm * 32 + 16) * 68 + kk * 8], 68);
            #pragma unroll
            for (int t = 0; t < 4; t++)
                wmma::load_matrix_sync(bf[t], &b[(wn * 64 + t * 16) * 68 + kk * 8], 68);
            #pragma unroll
            for (int t = 0; t < 4; t++) {
                wmma::mma_sync(acc[0][t], a0, bf[t], acc[0][t]);
                wmma::mma_sync(acc[1][t], a1, bf[t], acc[1][t]);
            }
        }
        __syncthreads();
        if (it + 2 < nKc) issue(it + 2);
    }

    float* sC = sm;
    #pragma unroll
    for (int i = 0; i < 2; i++)
        #pragma unroll
        for (int t = 0; t < 4; t++)
            wmma::store_matrix_sync(&sC[(wm * 32 + i * 16) * 132 + wn * 64 + t * 16],
                                    acc[i][t], 132, wmma::mem_row_major);
    __syncthreads();

    for (int idx = tid; idx < 128 * 128; idx += 256) {
        int m = idx >> 7, n = idx & 127;
        float v = sC[m * 132 + n];
        if (bias) v += bias[n0 + n];
        {   // mode 3: Weff -> fp16 rec image (+Whh_d)
            int gr = m0 + m, k = n0 + n;
            v += addm[(size_t)gr * ldc + k];
            int g = gr >> 10, cc = gr & 1023, nt2 = cc >> 4, r = g * 16 + (cc & 15);
            ((__half*)C)[(((size_t)nt2 * 8 + (k >> 7)) * 64 + r) * 136 + (k & 127)] =
                __float2half(v);
        }
    }
}

// ---------------- fp16 GEMM on packed operands ----------------
// C = A * B^T. mode 1: P store (+bias), coalesced [s][cta][m][col]. mode 2: final out remap (+bias).
__global__ void __launch_bounds__(256) k_gemmH(
        const __half* __restrict__ Apk, const __half* __restrict__ Bpk,
        float* __restrict__ C, int K,
        const float* __restrict__ bias, int mode) {
    extern __shared__ char smh[];
    __half* sm = (__half*)smh;
    unsigned sbase = (unsigned)__cvta_generic_to_shared(smh);
    unsigned barb  = sbase + 4 * HA * 2;
    const int tid = threadIdx.x;
    const int m0 = blockIdx.y * 128, n0 = blockIdx.x * 128;
    const int w = tid >> 5, wm = w >> 1, wn = w & 1;
    const int nKc = K >> 7;

    if (tid < 2) mbar_init(barb + tid * 8, 1);
    __syncthreads();

    auto issue = [&](int i) {
        if (tid == 0) {
            int st = i & 1;
            mbar_expect(barb + st * 8, 2 * HA * 2);
            bulk_g2s(sbase + (unsigned)(st * HA) * 2,
                     Apk + ((size_t)blockIdx.y * nKc + i) * HA, HA * 2, barb + st * 8);
            bulk_g2s(sbase + (unsigned)((2 + st) * HA) * 2,
                     Bpk + ((size_t)blockIdx.x * nKc + i) * HA, HA * 2, barb + st * 8);
        }
    };

    wmma::fragment<wmma::accumulator, 16, 16, 16, float> acc[2][4];
    #pragma unroll
    for (int i = 0; i < 2; i++)
        #pragma unroll
        for (int j = 0; j < 4; j++) wmma::fill_fragment(acc[i][j], 0.f);

    issue(0);
    if (nKc > 1) issue(1);

    for (int it = 0; it < nKc; it++) {
        int st = it & 1;
        mbar_wait(barb + st * 8, (it >> 1) & 1);
        const __half* a = sm + st * HA;
        const __half* b = sm + (2 + st) * HA;
        #pragma unroll
        for (int kk = 0; kk < 8; kk++) {
            wmma::fragment<wmma::matrix_a, 16, 16, 16, __half, wmma::row_major> a0, a1;
            wmma::fragment<wmma::matrix_b, 16, 16, 16, __half, wmma::col_major> bf[4];
            wmma::load_matrix_sync(a0, &a[(size_t)(wm * 32) * 136 + kk * 16], 136);
            wmma::load_matrix_sync(a1, &a[(size_t)(wm * 32 + 16) * 136 + kk * 16], 136);
            #pragma unroll
            for (int t = 0; t < 4; t++)
                wmma::load_matrix_sync(bf[t], &b[(size_t)(wn * 64 + t * 16) * 136 + kk * 16], 136);
            #pragma unroll
            for (int t = 0; t < 4; t++) {
                wmma::mma_sync(acc[0][t], a0, bf[t], acc[0][t]);
                wmma::mma_sync(acc[1][t], a1, bf[t], acc[1][t]);
            }
        }
        __syncthreads();
        if (it + 2 < nKc) issue(it + 2);
    }

    float* sC = (float*)smh;
    #pragma unroll
    for (int i = 0; i < 2; i++)
        #pragma unroll
        for (int t = 0; t < 4; t++)
            wmma::store_matrix_sync(&sC[(wm * 32 + i * 16) * 132 + wn * 64 + t * 16],
                                    acc[i][t], 132, wmma::mem_row_major);
    __syncthreads();

    for (int idx = tid; idx < 128 * 128; idx += 256) {
        int n = idx & 127, m = idx >> 7;          // n-minor: coalesced stores
        float v = sC[m * 132 + n];
        if (bias) v += bias[n0 + n];
        if (mode == 1) {            // P: GEMM row r = b*256+s -> Ppk[s][cta][m][col]
            int r = m0 + m, ng = n0 + n;
            int bb = r >> 8, s = r & 255;
            int g = ng >> 10, cc = ng & 1023, nt2 = cc >> 4, j = cc & 15;
            int cta = 2 * nt2 + (bb >> 6);
            C[(((size_t)s * 128 + cta) * 64 + (bb & 63)) * 64 + g * 16 + j] = v;
        } else {                    // final: r = t*128+b -> out[b][t][n]
            int r = m0 + m; int b = r & 127, t = r >> 7;
            C[((size_t)b * TT + t) * OO + n0 + n] = v;
        }
    }
}

// ---------------- persistent fp16 recurrence (R12 body + early-issue under barrier) --
// smem bytes: A 2x18432 @0 | Wres 8x17408 @36864 | sC0 @176128 | sC1 @193536 | bars @210944
#define RS_W    36864u
#define RS_C0   176128u
#define RS_C1   193536u
#define RS_BAR  210944u
#define RS_SMEM 210960

__global__ void __launch_bounds__(256, 1) k_rec16(
        const float* __restrict__ Ppk,
        const __half* __restrict__ WtE,
        const __half* __restrict__ WtD,
        const __half* __restrict__ WtF,
        const float* __restrict__ bdec,
        const float* __restrict__ beff,
        __half* __restrict__ hT16,
        __half* __restrict__ Hall16) {
    extern __shared__ __align__(128) char smc[];
    __half* sA = (__half*)smc;
    __half* sW = (__half*)(smc + RS_W);
    float* sC0 = (float*)(smc + RS_C0);
    float* sC1 = (float*)(smc + RS_C1);
    unsigned sb   = (unsigned)__cvta_generic_to_shared(smc);
    unsigned barb = sb + RS_BAR;

    const int tid = threadIdx.x, cta = blockIdx.x;
    const int mt = cta & 1, nt = cta >> 1, nb = nt * 16;
    const int w = tid >> 5;
    const int wm = w & 1, wn = (w >> 1) & 1, wk = w >> 2;
    const int mloc = tid & 63, j0 = tid >> 6;

    if (tid < 2) mbar_init(barb + tid * 8, 1);
    __syncthreads();

    float cst[4];
    #pragma unroll
    for (int jj = 0; jj < 4; jj++) cst[jj] = 0.f;

    int epoch = 0;

    // issue chunk c for an arbitrary step context
    auto issue2 = [&](int c, const __half* As, const __half* Ws, bool wl) {
        int st = c & 1;
        unsigned tx = 18432u + (wl ? 17408u : 0u);
        mbar_expect(barb + st * 8, tx);
        bulk_g2s(sb + (unsigned)(st * 18432), As + (size_t)c * 9216,
                 18432, barb + st * 8);
        if (wl)
            bulk_g2s(sb + RS_W + (unsigned)c * 17408, Ws + (size_t)c * 8704,
                     17408, barb + st * 8);
    };

    // step-0 context + initial issue
    {
        const __half* As0 = hT16 + (size_t)mt * 73728;
        const __half* Ws0 = WtE + (size_t)nt * 69632;
        if (tid == 0) { issue2(0, As0, Ws0, true); issue2(1, As0, Ws0, true); }
    }

    for (int s = 0; s < NSTEP; s++) {
        const bool wload = (s == 0) || (s == SS) || (s == SS + 1);
        const __half* Wsrc = ((s < SS) ? WtE : ((s == SS) ? WtD : WtF))
                             + (size_t)nt * 69632;
        const __half* Asrc = hT16 + (size_t)((s & 1) * 2 + mt) * 73728;
        __half* Adst = hT16 + (size_t)(((s + 1) & 1) * 2 + mt) * 73728;

        // prefetch P / bias into registers: 4x float4 per thread (hidden behind MMAs)
        float pv[16];
        if (s < SS) {
            const float* Ps = Ppk + ((size_t)s * 128 + cta) * 4096 + mloc * 64 + 4 * j0;
            #pragma unroll
            for (int g = 0; g < 4; g++) {
                float4 t4 = *(const float4*)&Ps[g * 16];
                pv[g * 4 + 0] = t4.x; pv[g * 4 + 1] = t4.y;
                pv[g * 4 + 2] = t4.z; pv[g * 4 + 3] = t4.w;
            }
        } else {
            const float* gb = (s == SS) ? bdec : beff;
            #pragma unroll
            for (int g = 0; g < 4; g++) {
                float4 t4 = *(const float4*)&gb[g * 1024 + nb + 4 * j0];
                pv[g * 4 + 0] = t4.x; pv[g * 4 + 1] = t4.y;
                pv[g * 4 + 2] = t4.z; pv[g * 4 + 3] = t4.w;
            }
        }

        wmma::fragment<wmma::accumulator, 16, 16, 16, float> acc[2][2];
        #pragma unroll
        for (int i = 0; i < 2; i++)
            #pragma unroll
            for (int q = 0; q < 2; q++) wmma::fill_fragment(acc[i][q], 0.f);

        for (int c = 0; c < 8; c++) {
            int st = c & 1;
            mbar_wait(barb + st * 8, (c >> 1) & 1);
            const __half* A = sA + st * 9216;           // [k128][72m]
            const __half* Wc = sW + (size_t)c * 8704;   // [64r][136k]
            #pragma unroll
            for (int kk = 0; kk < 4; kk++) {
                int k0 = wk * 64 + kk * 16;
                wmma::fragment<wmma::matrix_a, 16, 16, 16, __half, wmma::col_major> a0, a1;
                wmma::fragment<wmma::matrix_b, 16, 16, 16, __half, wmma::col_major> b0, b1;
                wmma::load_matrix_sync(a0, &A[(size_t)k0 * 72 + wm * 32], 72);
                wmma::load_matrix_sync(a1, &A[(size_t)k0 * 72 + wm * 32 + 16], 72);
                wmma::load_matrix_sync(b0, &Wc[(size_t)(wn * 32) * 136 + k0], 136);
                wmma::load_matrix_sync(b1, &Wc[(size_t)(wn * 32 + 16) * 136 + k0], 136);
                wmma::mma_sync(acc[0][0], a0, b0, acc[0][0]);
                wmma::mma_sync(acc[0][1], a0, b1, acc[0][1]);
                wmma::mma_sync(acc[1][0], a1, b0, acc[1][0]);
                wmma::mma_sync(acc[1][1], a1, b1, acc[1][1]);
            }
            __syncthreads();
            if (tid == 0 && c + 2 < 8) issue2(c + 2, Asrc, Wsrc, wload);
        }

        float* sCd = (wk == 0) ? sC0 : sC1;
        #pragma unroll
        for (int i = 0; i < 2; i++)
            #pragma unroll
            for (int q = 0; q < 2; q++)
                wmma::store_matrix_sync(&sCd[(wm * 32 + i * 16) * 68 + wn * 32 + q * 16],
                                        acc[i][q], 68, wmma::mem_row_major);
        __syncthreads();

        // pointwise: thread (mloc, j0) owns j = 4*j0 + jj (matches float4 P layout)
        #pragma unroll
        for (int jj = 0; jj < 4; jj++) {
            int j = 4 * j0 + jj;
            int n = nb + j;
            float Gi = sC0[mloc * 68 + j]      + sC1[mloc * 68 + j]      + pv[jj];
            float Gf = sC0[mloc * 68 + 16 + j] + sC1[mloc * 68 + 16 + j] + pv[4 + jj];
            float Gg = sC0[mloc * 68 + 32 + j] + sC1[mloc * 68 + 32 + j] + pv[8 + jj];
            float Go = sC0[mloc * 68 + 48 + j] + sC1[mloc * 68 + 48 + j] + pv[12 + jj];
            float si = 1.f / (1.f + __expf(-Gi));
            float sf = 1.f / (1.f + __expf(-Gf));
            float so = 1.f / (1.f + __expf(-Go));
            float tg = __fdividef(2.f, 1.f + __expf(-2.f * Gg)) - 1.f;
            float cn = sf * cst[jj] + si * tg;
            cst[jj] = cn;
            float tc = __fdividef(2.f, 1.f + __expf(-2.f * cn)) - 1.f;
            float hn = so * tc;
            Adst[((size_t)(n >> 7) * 128 + (n & 127)) * 72 + mloc] = __float2half(hn);
            if (s >= SS) {
                int t = s - SS;
                Hall16[(((size_t)t * 8 + (n >> 7)) * 128 + mt * 64 + mloc) * 136 + (n & 127)]
                    = __float2half(hn);
            }
        }

        // barrier with early issue of next step's chunks 0,1 right after the poll
        if (s < NSTEP - 1) {
            epoch++;
            __threadfence();
            __syncthreads();
            if (tid == 0) {
                atomicAdd(&g_bar2[mt], 1u);
                const unsigned tgt = 64u * (unsigned)epoch;
                volatile unsigned* p = &g_bar2[mt];
                while (*p < tgt) { }
                int s2 = s + 1;
                const bool wl2 = (s2 == SS) || (s2 == SS + 1);
                const __half* Ws2 = ((s2 < SS) ? WtE : ((s2 == SS) ? WtD : WtF))
                                    + (size_t)nt * 69632;
                const __half* As2 = hT16 + (size_t)((s2 & 1) * 2 + mt) * 73728;
                issue2(0, As2, Ws2, wl2);
                issue2(1, As2, Ws2, wl2);
            }
            __syncthreads();
        }
    }
}

// ---------------- host launch ----------------
extern "C" void kernel_launch(void* const* d_in, const int* in_sizes, int n_in,
                              void* d_out, int out_size) {
    int wbase = (n_in >= 12 && in_sizes[1] == 1) ? 2 : 1;

    const float* x     = (const float*)d_in[0];
    const float* Wih_e = (const float*)d_in[wbase + 0];
    const float* Whh_e = (const float*)d_in[wbase + 1];
    const float* bih_e = (const float*)d_in[wbase + 2];
    const float* bhh_e = (const float*)d_in[wbase + 3];
    const float* Wih_d = (const float*)d_in[wbase + 4];
    const float* Whh_d = (const float*)d_in[wbase + 5];
    const float* bih_d = (const float*)d_in[wbase + 6];
    const float* bhh_d = (const float*)d_in[wbase + 7];
    const float* Wproj = (const float*)d_in[wbase + 8];
    const float* bproj = (const float*)d_in[wbase + 9];
    float* out = (float*)d_out;

    float *Ppk, *WihDpk, *WpTpk, *benc, *bdec, *beff;
    __half *xpk16, *WihE16, *Wproj16, *Hall16, *WtE, *WtD, *WtF, *hT16;
    cudaGetSymbolAddress((void**)&Ppk,     g_Ppk);
    cudaGetSymbolAddress((void**)&xpk16,   g_xpk16);
    cudaGetSymbolAddress((void**)&WihE16,  g_WihE16);
    cudaGetSymbolAddress((void**)&Wproj16, g_Wproj16);
    cudaGetSymbolAddress((void**)&Hall16,  g_Hall16);
    cudaGetSymbolAddress((void**)&WihDpk,  g_WihDpk);
    cudaGetSymbolAddress((void**)&WpTpk,   g_WpTpk);
    cudaGetSymbolAddress((void**)&WtE,     g_Wt16E);
    cudaGetSymbolAddress((void**)&WtD,     g_Wt16D);
    cudaGetSymbolAddress((void**)&WtF,     g_Wt16F);
    cudaGetSymbolAddress((void**)&hT16,    g_hT16);
    cudaGetSymbolAddress((void**)&benc,    g_benc);
    cudaGetSymbolAddress((void**)&bdec,    g_bdec);
    cudaGetSymbolAddress((void**)&beff,    g_beff);

    const int gemmSmemB = 4 * GA * 4 + 64;
    const int gemmSmemH = 4 * HA * 2 + 64;
    cudaFuncSetAttribute(k_gemmB, cudaFuncAttributeMaxDynamicSharedMemorySize, gemmSmemB);
    cudaFuncSetAttribute(k_gemmH, cudaFuncAttributeMaxDynamicSharedMemorySize, gemmSmemH);
    cudaFuncSetAttribute(k_rec16, cudaFuncAttributeMaxDynamicSharedMemorySize, RS_SMEM);

    // biases
    k_vec_add<<<16, 256>>>(bih_e, bhh_e, benc, G4H);
    k_vec_add<<<16, 256>>>(bih_d, bhh_d, bdec, G4H);
    k_beff<<<16, 256>>>(Wih_d, bproj, bdec, beff);

    // fp16 packs (P + final GEMM operands)
    k_pack16<<<(int)(((size_t)BB * SS * II / 4 + 255) / 256), 256>>>(
        x, xpk16, II, (size_t)BB * SS * II);
    k_pack16<<<(int)(((size_t)G4H * II / 4 + 255) / 256), 256>>>(
        Wih_e, WihE16, II, (size_t)G4H * II);
    k_pack16<<<(int)(((size_t)OO * HH / 4 + 255) / 256), 256>>>(
        Wproj, Wproj16, HH, (size_t)OO * HH);
    // tf32 packs (Weff GEMM operands)
    k_pack<<<(int)(((size_t)G4H * OO / 4 + 255) / 256), 256>>>(
        Wih_d, WihDpk, OO, (size_t)G4H * OO);
    k_pack_T<<<(HH * OO + 255) / 256, 256>>>(Wproj, WpTpk);
    // rec weight images
    k_pack_w16<<<(64 * 8 * 64 * 128) / 256, 256>>>(Whh_e, WtE);
    k_pack_w16<<<(64 * 8 * 64 * 128) / 256, 256>>>(Whh_d, WtD);

    // W_eff = W_ih_dec @ W_proj + W_hh_dec -> fp16 rec image (tf32 GEMM, mode 3)
    k_gemmB<<<dim3(HH / 128, G4H / 128), 256, gemmSmemB>>>(
        WihDpk, WpTpk, (float*)WtF, HH, OO, nullptr, Whh_d, 3);

    // P = X @ W_ih_enc^T + b_enc -> Ppk (fp16 GEMM, mode 1, coalesced store)
    k_gemmH<<<dim3(G4H / 128, (BB * SS) / 128), 256, gemmSmemH>>>(
        xpk16, WihE16, Ppk, II, benc, 1);

    // zero h images, reset barrier, run the 384-step recurrence
    k_zero<<<(2 * 2 * 8 * 128 * 72 / 2 + 255) / 256, 256>>>((float*)hT16,
                                                            2 * 2 * 8 * 128 * 72 / 2);
    k_reset_bar<<<1, 1>>>();
    k_rec16<<<NCTA_REC, 256, RS_SMEM>>>(Ppk, WtE, WtD, WtF, bdec, beff, hT16, Hall16);

    // Y = Hall @ W_proj^T + b_proj -> out[b][t][o] (fp16 GEMM, mode 2)
    k_gemmH<<<dim3(OO / 128, (BB * TT) / 128), 256, gemmSmemH>>>(
        Hall16, Wproj16, out, HH, bproj, 2);
}

// round 17
// speedup vs baseline: 1.1141x; 1.0142x over previous
#include <cuda_runtime.h>
#include <cuda_fp16.h>
#include <mma.h>
#include <math.h>

using namespace nvcuda;

#define BB  128
#define SS  256
#define II  512
#define HH  1024
#define OO  512
#define TT  128
#define G4H 4096
#define NSTEP (SS + TT)
#define NCTA_REC 128
#define GA 8704            // floats per packed 128x68 K-chunk tile (tf32 GEMM)
#define HA 17408           // halves per packed 128x136 K-chunk tile (fp16 GEMM)

// ---------------- static device scratch ----------------
__device__ __align__(128) float g_Ppk[(size_t)SS * 128 * 4096];   // P [s][cta][m64][col64]
__device__ __align__(128) __half g_xpk16[(size_t)256 * 4 * HA];
__device__ __align__(128) __half g_WihE16[(size_t)32 * 4 * HA];
__device__ __align__(128) __half g_Wproj16[(size_t)4 * 8 * HA];
__device__ __align__(128) __half g_Hall16[(size_t)128 * 8 * HA];  // decoder h fp16 packed
__device__ __align__(128) float g_WihDpk[(size_t)32 * 8 * GA];    // tf32 packs (Weff GEMM)
__device__ __align__(128) float g_WpTpk[(size_t)8 * 8 * GA];
__device__ __align__(128) __half g_Wt16E[(size_t)64 * 8 * 8704];  // rec W images [nt][ch][64r][136k]
__device__ __align__(128) __half g_Wt16D[(size_t)64 * 8 * 8704];
__device__ __align__(128) __half g_Wt16F[(size_t)64 * 8 * 8704];
__device__ __align__(128) __half g_hT16[2 * 2 * 8 * 128 * 72];    // [buf][mt][ch][128k][72m]
__device__ float g_benc[G4H];
__device__ float g_bdec[G4H];
__device__ float g_beff[G4H];
__device__ unsigned g_bar2[2];

// ---------------- helpers ----------------
__device__ __forceinline__ float tf32t(float x) {
    unsigned u;
    asm("cvt.rna.tf32.f32 %0, %1;" : "=r"(u) : "f"(x));
    return __uint_as_float(u);
}
__device__ __forceinline__ void mbar_init(unsigned mbar, unsigned cnt) {
    asm volatile("mbarrier.init.shared.b64 [%0], %1;" :: "r"(mbar), "r"(cnt) : "memory");
}
__device__ __forceinline__ void mbar_expect(unsigned mbar, unsigned bytes) {
    asm volatile("mbarrier.arrive.expect_tx.shared.b64 _, [%0], %1;"
                 :: "r"(mbar), "r"(bytes) : "memory");
}
__device__ __forceinline__ void mbar_wait(unsigned mbar, unsigned parity) {
    unsigned done = 0;
    while (!done) {
        asm volatile(
            "{\n\t.reg .pred p;\n\t"
            "mbarrier.try_wait.parity.acquire.cta.shared::cta.b64 p, [%1], %2, 0x989680;\n\t"
            "selp.b32 %0, 1, 0, p;\n\t}"
            : "=r"(done) : "r"(mbar), "r"(parity) : "memory");
    }
}
__device__ __forceinline__ void bulk_g2s(unsigned dst, const void* src, unsigned bytes,
                                         unsigned mbar) {
    asm volatile(
        "cp.async.bulk.shared::cluster.global.mbarrier::complete_tx::bytes [%0], [%1], %2, [%3];"
        :: "r"(dst), "l"(src), "r"(bytes), "r"(mbar) : "memory");
}

__global__ void k_reset_bar() { g_bar2[0] = 0u; g_bar2[1] = 0u; }

// ---------------- small kernels ----------------
__global__ void k_zero(float* p, int n) {
    int i = blockIdx.x * blockDim.x + threadIdx.x;
    if (i < n) p[i] = 0.f;
}
__global__ void k_vec_add(const float* __restrict__ a, const float* __restrict__ b,
                          float* __restrict__ o, int n) {
    int i = blockIdx.x * blockDim.x + threadIdx.x;
    if (i < n) o[i] = a[i] + b[i];
}
__global__ void k_beff(const float* __restrict__ Wih, const float* __restrict__ bproj,
                       const float* __restrict__ bdec, float* __restrict__ beff) {
    int n = blockIdx.x * blockDim.x + threadIdx.x;
    if (n < G4H) {
        float s = bdec[n];
        const float* wr = Wih + (size_t)n * OO;
        #pragma unroll 8
        for (int o = 0; o < OO; o++) s += wr[o] * bproj[o];
        beff[n] = s;
    }
}
// tf32 pack: src [M][K] -> [mtile][kc64][128][68]
__global__ void k_pack(const float* __restrict__ src, float* __restrict__ dst,
                       int K, size_t total) {
    size_t i = ((size_t)blockIdx.x * 256 + threadIdx.x) * 4;
    if (i < total) {
        int r = (int)(i / (unsigned)K);
        int k = (int)(i - (size_t)r * K);
        float4 v = *(const float4*)&src[i];
        v.x = tf32t(v.x); v.y = tf32t(v.y); v.z = tf32t(v.z); v.w = tf32t(v.w);
        int nk = K >> 6;
        size_t d = ((size_t)(r >> 7) * nk + (k >> 6)) * GA + (r & 127) * 68 + (k & 63);
        *(float4*)&dst[d] = v;
    }
}
// fp16 pack: src [M][K] -> [mtile][kc128][128][136]
__global__ void k_pack16(const float* __restrict__ src, __half* __restrict__ dst,
                         int K, size_t total) {
    size_t i = ((size_t)blockIdx.x * 256 + threadIdx.x) * 4;
    if (i < total) {
        int r = (int)(i / (unsigned)K);
        int k = (int)(i - (size_t)r * K);
        float4 v = *(const float4*)&src[i];
        __half2 h0 = __floats2half2_rn(v.x, v.y);
        __half2 h1 = __floats2half2_rn(v.z, v.w);
        int nk = K >> 7;
        size_t d = ((size_t)(r >> 7) * nk + (k >> 7)) * HA + (r & 127) * 136 + (k & 127);
        *(__half2*)&dst[d]     = h0;
        *(__half2*)&dst[d + 2] = h1;
    }
}
// pack transpose of Wproj [O][H] as tf32 B operand rows n (N=1024, K=512)
__global__ void k_pack_T(const float* __restrict__ Wproj, float* __restrict__ dst) {
    int i = blockIdx.x * blockDim.x + threadIdx.x;
    if (i < HH * OO) {
        int n = i >> 9, o = i & 511;
        float v = tf32t(Wproj[(size_t)o * HH + n]);
        size_t d = ((size_t)(n >> 7) * 8 + (o >> 6)) * GA + (n & 127) * 68 + (o & 63);
        dst[d] = v;
    }
}
// W [4H][H] fp32 -> fp16 rec image [nt64][ch8][row64][136]
__global__ void k_pack_w16(const float* __restrict__ W, __half* __restrict__ dst) {
    int i = blockIdx.x * blockDim.x + threadIdx.x;
    if (i < 64 * 8 * 64 * 128) {
        int kl = i & 127, r = (i >> 7) & 63, ch = (i >> 13) & 7, nt = i >> 16;
        int gr = (r >> 4) * 1024 + nt * 16 + (r & 15);
        dst[(((size_t)nt * 8 + ch) * 64 + r) * 136 + kl] =
            __float2half(W[(size_t)gr * HH + ch * 128 + kl]);
    }
}

// ---------------- tf32 GEMM (Weff only, mode 3) ----------------
__global__ void __launch_bounds__(256) k_gemmB(
        const float* __restrict__ Apk, const float* __restrict__ Bpk,
        float* __restrict__ C, int ldc, int K,
        const float* __restrict__ bias, const float* __restrict__ addm, int mode) {
    extern __shared__ float sm[];
    unsigned sbase = (unsigned)__cvta_generic_to_shared(sm);
    unsigned barb  = sbase + 4 * GA * 4;
    const int tid = threadIdx.x;
    const int m0 = blockIdx.y * 128, n0 = blockIdx.x * 128;
    const int w = tid >> 5, wm = w >> 1, wn = w & 1;
    const int nKc = K >> 6;

    if (tid < 2) mbar_init(barb + tid * 8, 1);
    __syncthreads();

    auto issue = [&](int i) {
        if (tid == 0) {
            int st = i & 1;
            mbar_expect(barb + st * 8, 2 * GA * 4);
            bulk_g2s(sbase + (unsigned)(st * GA) * 4,
                     Apk + ((size_t)blockIdx.y * nKc + i) * GA, GA * 4, barb + st * 8);
            bulk_g2s(sbase + (unsigned)((2 + st) * GA) * 4,
                     Bpk + ((size_t)blockIdx.x * nKc + i) * GA, GA * 4, barb + st * 8);
        }
    };

    wmma::fragment<wmma::accumulator, 16, 16, 8, float> acc[2][4];
    #pragma unroll
    for (int i = 0; i < 2; i++)
        #pragma unroll
        for (int j = 0; j < 4; j++) wmma::fill_fragment(acc[i][j], 0.f);

    issue(0);
    if (nKc > 1) issue(1);

    for (int it = 0; it < nKc; it++) {
        int st = it & 1;
        mbar_wait(barb + st * 8, (it >> 1) & 1);
        const float* a = sm + st * GA;
        const float* b = sm + (2 + st) * GA;
        #pragma unroll
        for (int kk = 0; kk < 8; kk++) {
            wmma::fragment<wmma::matrix_a, 16, 16, 8, wmma::precision::tf32, wmma::row_major> a0, a1;
            wmma::fragment<wmma::matrix_b, 16, 16, 8, wmma::precision::tf32, wmma::col_major> bf[4];
            wmma::load_matrix_sync(a0, &a[(wm * 32) * 68 + kk * 8], 68);
            wmma::load_matrix_sync(a1, &a[(wm * 32 + 16) * 68 + kk * 8], 68);
            #pragma unroll
            for (int t = 0; t < 4; t++)
                wmma::load_matrix_sync(bf[t], &b[(wn * 64 + t * 16) * 68 + kk * 8], 68);
            #pragma unroll
            for (int t = 0; t < 4; t++) {
                wmma::mma_sync(acc[0][t], a0, bf[t], acc[0][t]);
                wmma::mma_sync(acc[1][t], a1, bf[t], acc[1][t]);
            }
        }
        __syncthreads();
        if (it + 2 < nKc) issue(it + 2);
    }

    float* sC = sm;
    #pragma unroll
    for (int i = 0; i < 2; i++)
        #pragma unroll
        for (int t = 0; t < 4; t++)
            wmma::store_matrix_sync(&sC[(wm * 32 + i * 16) * 132 + wn * 64 + t * 16],
                                    acc[i][t], 132, wmma::mem_row_major);
    __syncthreads();

    for (int idx = tid; idx < 128 * 128; idx += 256) {
        int m = idx >> 7, n = idx & 127;
        float v = sC[m * 132 + n];
        if (bias) v += bias[n0 + n];
        {   // mode 3: Weff -> fp16 rec image (+Whh_d)
            int gr = m0 + m, k = n0 + n;
            v += addm[(size_t)gr * ldc + k];
            int g = gr >> 10, cc = gr & 1023, nt2 = cc >> 4, r = g * 16 + (cc & 15);
            ((__half*)C)[(((size_t)nt2 * 8 + (k >> 7)) * 64 + r) * 136 + (k & 127)] =
                __float2half(v);
        }
    }
}

// ---------------- fp16 GEMM on packed operands ----------------
// C = A * B^T. mode 1: P store (+bias), coalesced [s][cta][m][col]. mode 2: final out remap (+bias).
__global__ void __launch_bounds__(256) k_gemmH(
        const __half* __restrict__ Apk, const __half* __restrict__ Bpk,
        float* __restrict__ C, int K,
        const float* __restrict__ bias, int mode) {
    extern __shared__ char smh[];
    __half* sm = (__half*)smh;
    unsigned sbase = (unsigned)__cvta_generic_to_shared(smh);
    unsigned barb  = sbase + 4 * HA * 2;
    const int tid = threadIdx.x;
    const int m0 = blockIdx.y * 128, n0 = blockIdx.x * 128;
    const int w = tid >> 5, wm = w >> 1, wn = w & 1;
    const int nKc = K >> 7;

    if (tid < 2) mbar_init(barb + tid * 8, 1);
    __syncthreads();

    auto issue = [&](int i) {
        if (tid == 0) {
            int st = i & 1;
            mbar_expect(barb + st * 8, 2 * HA * 2);
            bulk_g2s(sbase + (unsigned)(st * HA) * 2,
                     Apk + ((size_t)blockIdx.y * nKc + i) * HA, HA * 2, barb + st * 8);
            bulk_g2s(sbase + (unsigned)((2 + st) * HA) * 2,
                     Bpk + ((size_t)blockIdx.x * nKc + i) * HA, HA * 2, barb + st * 8);
        }
    };

    wmma::fragment<wmma::accumulator, 16, 16, 16, float> acc[2][4];
    #pragma unroll
    for (int i = 0; i < 2; i++)
        #pragma unroll
        for (int j = 0; j < 4; j++) wmma::fill_fragment(acc[i][j], 0.f);

    issue(0);
    if (nKc > 1) issue(1);

    for (int it = 0; it < nKc; it++) {
        int st = it & 1;
        mbar_wait(barb + st * 8, (it >> 1) & 1);
        const __half* a = sm + st * HA;
        const __half* b = sm + (2 + st) * HA;
        #pragma unroll
        for (int kk = 0; kk < 8; kk++) {
            wmma::fragment<wmma::matrix_a, 16, 16, 16, __half, wmma::row_major> a0, a1;
            wmma::fragment<wmma::matrix_b, 16, 16, 16, __half, wmma::col_major> bf[4];
            wmma::load_matrix_sync(a0, &a[(size_t)(wm * 32) * 136 + kk * 16], 136);
            wmma::load_matrix_sync(a1, &a[(size_t)(wm * 32 + 16) * 136 + kk * 16], 136);
            #pragma unroll
            for (int t = 0; t < 4; t++)
                wmma::load_matrix_sync(bf[t], &b[(size_t)(wn * 64 + t * 16) * 136 + kk * 16], 136);
            #pragma unroll
            for (int t = 0; t < 4; t++) {
                wmma::mma_sync(acc[0][t], a0, bf[t], acc[0][t]);
                wmma::mma_sync(acc[1][t], a1, bf[t], acc[1][t]);
            }
        }
        __syncthreads();
        if (it + 2 < nKc) issue(it + 2);
    }

    float* sC = (float*)smh;
    #pragma unroll
    for (int i = 0; i < 2; i++)
        #pragma unroll
        for (int t = 0; t < 4; t++)
            wmma::store_matrix_sync(&sC[(wm * 32 + i * 16) * 132 + wn * 64 + t * 16],
                                    acc[i][t], 132, wmma::mem_row_major);
    __syncthreads();

    for (int idx = tid; idx < 128 * 128; idx += 256) {
        int n = idx & 127, m = idx >> 7;          // n-minor: coalesced stores
        float v = sC[m * 132 + n];
        if (bias) v += bias[n0 + n];
        if (mode == 1) {            // P: GEMM row r = b*256+s -> Ppk[s][cta][m][col]
            int r = m0 + m, ng = n0 + n;
            int bb = r >> 8, s = r & 255;
            int g = ng >> 10, cc = ng & 1023, nt2 = cc >> 4, j = cc & 15;
            int cta = 2 * nt2 + (bb >> 6);
            C[(((size_t)s * 128 + cta) * 64 + (bb & 63)) * 64 + g * 16 + j] = v;
        } else {                    // final: r = t*128+b -> out[b][t][n]
            int r = m0 + m; int b = r & 127, t = r >> 7;
            C[((size_t)b * TT + t) * OO + n0 + n] = v;
        }
    }
}

// ---------------- persistent fp16 recurrence (4 x k=256 chunks, sC overlays A stage0) --
// smem bytes: A 2x36864 @0 | Wres 8x17408 @73728 | sC0 @0 sC1 @17408 (overlay) | bars @212992
#define RS_W    73728u
#define RS_C1   17408u
#define RS_BAR  212992u
#define RS_SMEM 213056

__global__ void __launch_bounds__(256, 1) k_rec16(
        const float* __restrict__ Ppk,
        const __half* __restrict__ WtE,
        const __half* __restrict__ WtD,
        const __half* __restrict__ WtF,
        const float* __restrict__ bdec,
        const float* __restrict__ beff,
        __half* __restrict__ hT16,
        __half* __restrict__ Hall16) {
    extern __shared__ __align__(128) char smc[];
    __half* sA = (__half*)smc;                 // 2 stages x 36864 B
    __half* sW = (__half*)(smc + RS_W);        // 8 x 17408 B
    float* sC0 = (float*)smc;                  // overlay on A stage 0
    float* sC1 = (float*)(smc + RS_C1);
    unsigned sb   = (unsigned)__cvta_generic_to_shared(smc);
    unsigned barb = sb + RS_BAR;

    const int tid = threadIdx.x, cta = blockIdx.x;
    const int mt = cta & 1, nt = cta >> 1, nb = nt * 16;
    const int w = tid >> 5;
    const int wm = w & 1, wn = (w >> 1) & 1, wk = w >> 2;
    const int mloc = tid & 63, j0 = tid >> 6;

    if (tid < 2) mbar_init(barb + tid * 8, 1);
    __syncthreads();

    float cst[4];
    #pragma unroll
    for (int jj = 0; jj < 4; jj++) cst[jj] = 0.f;

    int epoch = 0;

    // issue double-chunk c (k = c*256 .. +256) for an arbitrary step context
    auto issue2 = [&](int c, const __half* As, const __half* Ws, bool wl) {
        int st = c & 1;
        unsigned tx = 36864u + (wl ? 34816u : 0u);
        mbar_expect(barb + st * 8, tx);
        bulk_g2s(sb + (unsigned)(st * 36864), As + (size_t)c * 18432,
                 36864, barb + st * 8);
        if (wl)
            bulk_g2s(sb + RS_W + (unsigned)c * 34816, Ws + (size_t)c * 17408,
                     34816, barb + st * 8);
    };

    // step-0 context + initial issue
    {
        const __half* As0 = hT16 + (size_t)mt * 73728;
        const __half* Ws0 = WtE + (size_t)nt * 69632;
        if (tid == 0) { issue2(0, As0, Ws0, true); issue2(1, As0, Ws0, true); }
    }

    for (int s = 0; s < NSTEP; s++) {
        const bool wload = (s == 0) || (s == SS) || (s == SS + 1);
        const __half* Wsrc = ((s < SS) ? WtE : ((s == SS) ? WtD : WtF))
                             + (size_t)nt * 69632;
        const __half* Asrc = hT16 + (size_t)((s & 1) * 2 + mt) * 73728;
        __half* Adst = hT16 + (size_t)(((s + 1) & 1) * 2 + mt) * 73728;

        // prefetch P / bias into registers: 4x float4 per thread (hidden behind MMAs)
        float pv[16];
        if (s < SS) {
            const float* Ps = Ppk + ((size_t)s * 128 + cta) * 4096 + mloc * 64 + 4 * j0;
            #pragma unroll
            for (int g = 0; g < 4; g++) {
                float4 t4 = *(const float4*)&Ps[g * 16];
                pv[g * 4 + 0] = t4.x; pv[g * 4 + 1] = t4.y;
                pv[g * 4 + 2] = t4.z; pv[g * 4 + 3] = t4.w;
            }
        } else {
            const float* gb = (s == SS) ? bdec : beff;
            #pragma unroll
            for (int g = 0; g < 4; g++) {
                float4 t4 = *(const float4*)&gb[g * 1024 + nb + 4 * j0];
                pv[g * 4 + 0] = t4.x; pv[g * 4 + 1] = t4.y;
                pv[g * 4 + 2] = t4.z; pv[g * 4 + 3] = t4.w;
            }
        }

        wmma::fragment<wmma::accumulator, 16, 16, 16, float> acc[2][2];
        #pragma unroll
        for (int i = 0; i < 2; i++)
            #pragma unroll
            for (int q = 0; q < 2; q++) wmma::fill_fragment(acc[i][q], 0.f);

        for (int c = 0; c < 4; c++) {
            int st = c & 1;
            mbar_wait(barb + st * 8, (c >> 1) & 1);
            const __half* A = sA + st * 18432;              // [2x[128k][72m]]
            const __half* Wc = sW + (size_t)(2 * c + wk) * 8704;   // [64r][136k]
            const __half* Aw = A + wk * 9216;
            #pragma unroll
            for (int kk = 0; kk < 8; kk++) {
                wmma::fragment<wmma::matrix_a, 16, 16, 16, __half, wmma::col_major> a0, a1;
                wmma::fragment<wmma::matrix_b, 16, 16, 16, __half, wmma::col_major> b0, b1;
                wmma::load_matrix_sync(a0, &Aw[(size_t)kk * 1152 + wm * 32], 72);
                wmma::load_matrix_sync(a1, &Aw[(size_t)kk * 1152 + wm * 32 + 16], 72);
                wmma::load_matrix_sync(b0, &Wc[(size_t)(wn * 32) * 136 + kk * 16], 136);
                wmma::load_matrix_sync(b1, &Wc[(size_t)(wn * 32 + 16) * 136 + kk * 16], 136);
                wmma::mma_sync(acc[0][0], a0, b0, acc[0][0]);
                wmma::mma_sync(acc[0][1], a0, b1, acc[0][1]);
                wmma::mma_sync(acc[1][0], a1, b0, acc[1][0]);
                wmma::mma_sync(acc[1][1], a1, b1, acc[1][1]);
            }
            __syncthreads();
            if (tid == 0 && c + 2 < 4) issue2(c + 2, Asrc, Wsrc, wload);
        }

        float* sCd = (wk == 0) ? sC0 : sC1;
        #pragma unroll
        for (int i = 0; i < 2; i++)
            #pragma unroll
            for (int q = 0; q < 2; q++)
                wmma::store_matrix_sync(&sCd[(wm * 32 + i * 16) * 68 + wn * 32 + q * 16],
                                        acc[i][q], 68, wmma::mem_row_major);
        __syncthreads();

        // pointwise: thread (mloc, j0) owns j = 4*j0 + jj (matches float4 P layout)
        #pragma unroll
        for (int jj = 0; jj < 4; jj++) {
            int j = 4 * j0 + jj;
            int n = nb + j;
            float Gi = sC0[mloc * 68 + j]      + sC1[mloc * 68 + j]      + pv[jj];
            float Gf = sC0[mloc * 68 + 16 + j] + sC1[mloc * 68 + 16 + j] + pv[4 + jj];
            float Gg = sC0[mloc * 68 + 32 + j] + sC1[mloc * 68 + 32 + j] + pv[8 + jj];
            float Go = sC0[mloc * 68 + 48 + j] + sC1[mloc * 68 + 48 + j] + pv[12 + jj];
            float si = 1.f / (1.f + __expf(-Gi));
            float sf = 1.f / (1.f + __expf(-Gf));
            float so = 1.f / (1.f + __expf(-Go));
            float tg = __fdividef(2.f, 1.f + __expf(-2.f * Gg)) - 1.f;
            float cn = sf * cst[jj] + si * tg;
            cst[jj] = cn;
            float tc = __fdividef(2.f, 1.f + __expf(-2.f * cn)) - 1.f;
            float hn = so * tc;
            Adst[((size_t)(n >> 7) * 128 + (n & 127)) * 72 + mloc] = __float2half(hn);
            if (s >= SS) {
                int t = s - SS;
                Hall16[(((size_t)t * 8 + (n >> 7)) * 128 + mt * 64 + mloc) * 136 + (n & 127)]
                    = __float2half(hn);
            }
        }

        // barrier with early issue of next step's chunks 0,1 right after the poll
        if (s < NSTEP - 1) {
            epoch++;
            __threadfence();
            __syncthreads();
            if (tid == 0) {
                atomicAdd(&g_bar2[mt], 1u);
                const unsigned tgt = 64u * (unsigned)epoch;
                volatile unsigned* p = &g_bar2[mt];
                while (*p < tgt) { }
                int s2 = s + 1;
                const bool wl2 = (s2 == SS) || (s2 == SS + 1);
                const __half* Ws2 = ((s2 < SS) ? WtE : ((s2 == SS) ? WtD : WtF))
                                    + (size_t)nt * 69632;
                const __half* As2 = hT16 + (size_t)((s2 & 1) * 2 + mt) * 73728;
                issue2(0, As2, Ws2, wl2);
                issue2(1, As2, Ws2, wl2);
            }
            __syncthreads();
        }
    }
}

// ---------------- host launch ----------------
extern "C" void kernel_launch(void* const* d_in, const int* in_sizes, int n_in,
                              void* d_out, int out_size) {
    int wbase = (n_in >= 12 && in_sizes[1] == 1) ? 2 : 1;

    const float* x     = (const float*)d_in[0];
    const float* Wih_e = (const float*)d_in[wbase + 0];
    const float* Whh_e = (const float*)d_in[wbase + 1];
    const float* bih_e = (const float*)d_in[wbase + 2];
    const float* bhh_e = (const float*)d_in[wbase + 3];
    const float* Wih_d = (const float*)d_in[wbase + 4];
    const float* Whh_d = (const float*)d_in[wbase + 5];
    const float* bih_d = (const float*)d_in[wbase + 6];
    const float* bhh_d = (const float*)d_in[wbase + 7];
    const float* Wproj = (const float*)d_in[wbase + 8];
    const float* bproj = (const float*)d_in[wbase + 9];
    float* out = (float*)d_out;

    float *Ppk, *WihDpk, *WpTpk, *benc, *bdec, *beff;
    __half *xpk16, *WihE16, *Wproj16, *Hall16, *WtE, *WtD, *WtF, *hT16;
    cudaGetSymbolAddress((void**)&Ppk,     g_Ppk);
    cudaGetSymbolAddress((void**)&xpk16,   g_xpk16);
    cudaGetSymbolAddress((void**)&WihE16,  g_WihE16);
    cudaGetSymbolAddress((void**)&Wproj16, g_Wproj16);
    cudaGetSymbolAddress((void**)&Hall16,  g_Hall16);
    cudaGetSymbolAddress((void**)&WihDpk,  g_WihDpk);
    cudaGetSymbolAddress((void**)&WpTpk,   g_WpTpk);
    cudaGetSymbolAddress((void**)&WtE,     g_Wt16E);
    cudaGetSymbolAddress((void**)&WtD,     g_Wt16D);
    cudaGetSymbolAddress((void**)&WtF,     g_Wt16F);
    cudaGetSymbolAddress((void**)&hT16,    g_hT16);
    cudaGetSymbolAddress((void**)&benc,    g_benc);
    cudaGetSymbolAddress((void**)&bdec,    g_bdec);
    cudaGetSymbolAddress((void**)&beff,    g_beff);

    const int gemmSmemB = 4 * GA * 4 + 64;
    const int gemmSmemH = 4 * HA * 2 + 64;
    cudaFuncSetAttribute(k_gemmB, cudaFuncAttributeMaxDynamicSharedMemorySize, gemmSmemB);
    cudaFuncSetAttribute(k_gemmH, cudaFuncAttributeMaxDynamicSharedMemorySize, gemmSmemH);
    cudaFuncSetAttribute(k_rec16, cudaFuncAttributeMaxDynamicSharedMemorySize, RS_SMEM);

    // biases
    k_vec_add<<<16, 256>>>(bih_e, bhh_e, benc, G4H);
    k_vec_add<<<16, 256>>>(bih_d, bhh_d, bdec, G4H);
    k_beff<<<16, 256>>>(Wih_d, bproj, bdec, beff);

    // fp16 packs (P + final GEMM operands)
    k_pack16<<<(int)(((size_t)BB * SS * II / 4 + 255) / 256), 256>>>(
        x, xpk16, II, (size_t)BB * SS * II);
    k_pack16<<<(int)(((size_t)G4H * II / 4 + 255) / 256), 256>>>(
        Wih_e, WihE16, II, (size_t)G4H * II);
    k_pack16<<<(int)(((size_t)OO * HH / 4 + 255) / 256), 256>>>(
        Wproj, Wproj16, HH, (size_t)OO * HH);
    // tf32 packs (Weff GEMM operands)
    k_pack<<<(int)(((size_t)G4H * OO / 4 + 255) / 256), 256>>>(
        Wih_d, WihDpk, OO, (size_t)G4H * OO);
    k_pack_T<<<(HH * OO + 255) / 256, 256>>>(Wproj, WpTpk);
    // rec weight images
    k_pack_w16<<<(64 * 8 * 64 * 128) / 256, 256>>>(Whh_e, WtE);
    k_pack_w16<<<(64 * 8 * 64 * 128) / 256, 256>>>(Whh_d, WtD);

    // W_eff = W_ih_dec @ W_proj + W_hh_dec -> fp16 rec image (tf32 GEMM, mode 3)
    k_gemmB<<<dim3(HH / 128, G4H / 128), 256, gemmSmemB>>>(
        WihDpk, WpTpk, (float*)WtF, HH, OO, nullptr, Whh_d, 3);

    // P = X @ W_ih_enc^T + b_enc -> Ppk (fp16 GEMM, mode 1, coalesced store)
    k_gemmH<<<dim3(G4H / 128, (BB * SS) / 128), 256, gemmSmemH>>>(
        xpk16, WihE16, Ppk, II, benc, 1);

    // zero h images, reset barrier, run the 384-step recurrence
    k_zero<<<(2 * 2 * 8 * 128 * 72 / 2 + 255) / 256, 256>>>((float*)hT16,
                                                            2 * 2 * 8 * 128 * 72 / 2);
    k_reset_bar<<<1, 1>>>();
    k_rec16<<<NCTA_REC, 256, RS_SMEM>>>(Ppk, WtE, WtD, WtF, bdec, beff, hT16, Hall16);

    // Y = Hall @ W_proj^T + b_proj -> out[b][t][o] (fp16 GEMM, mode 2)
    k_gemmH<<<dim3(OO / 128, (BB * TT) / 128), 256, gemmSmemH>>>(
        Hall16, Wproj16, out, HH, bproj, 2);
}